// round 1
// baseline (speedup 1.0000x reference)
#include <cuda_runtime.h>
#include <cuda_bf16.h>

#define BATCH 2
#define SEQ 2048
#define DIM 2048
#define NH 32
#define NKV 8
#define HD 64
#define ATT_SCALE 0.125f

// Scratch (no cudaMalloc allowed)
__device__ float g_q[BATCH * SEQ * NH * HD];    // [b,s,h,d]
__device__ float g_k[BATCH * SEQ * NKV * HD];   // [b,s,kh,d]
__device__ float g_v[BATCH * SEQ * NKV * HD];   // [b,s,kh,d]
__device__ float g_o[BATCH * SEQ * NH * HD];    // [b,s,h,d]

// ---------------------------------------------------------------------------
// SGEMM: C[M,N] = A[M,K] @ B[K,N], row-major fp32. 128x128 tile, BK=8,
// 256 threads, 8x8 per thread. M%128==0, N%128==0, K%8==0 assumed.
// ---------------------------------------------------------------------------
__global__ __launch_bounds__(256) void sgemm128(
    const float* __restrict__ A, const float* __restrict__ B,
    float* __restrict__ C, int M, int N, int K)
{
    __shared__ float As[8][128];
    __shared__ float Bs[8][128];
    const int tid = threadIdx.x;
    const int tx = tid & 15, ty = tid >> 4;
    const int arow = tid >> 1, acol = (tid & 1) * 4;
    const int brow = tid >> 5, bcol = (tid & 31) * 4;

    const float* Aptr = A + (size_t)(blockIdx.y * 128 + arow) * K + acol;
    const float* Bptr = B + (size_t)brow * N + blockIdx.x * 128 + bcol;

    float acc[8][8];
#pragma unroll
    for (int i = 0; i < 8; i++)
#pragma unroll
        for (int j = 0; j < 8; j++) acc[i][j] = 0.f;

    for (int k0 = 0; k0 < K; k0 += 8) {
        float4 a4 = *(const float4*)Aptr;
        As[acol + 0][arow] = a4.x;
        As[acol + 1][arow] = a4.y;
        As[acol + 2][arow] = a4.z;
        As[acol + 3][arow] = a4.w;
        *(float4*)&Bs[brow][bcol] = *(const float4*)Bptr;
        __syncthreads();
#pragma unroll
        for (int kk = 0; kk < 8; kk++) {
            float a[8], b[8];
            *(float4*)&a[0] = *(const float4*)&As[kk][ty * 8];
            *(float4*)&a[4] = *(const float4*)&As[kk][ty * 8 + 4];
            *(float4*)&b[0] = *(const float4*)&Bs[kk][tx * 8];
            *(float4*)&b[4] = *(const float4*)&Bs[kk][tx * 8 + 4];
#pragma unroll
            for (int i = 0; i < 8; i++)
#pragma unroll
                for (int j = 0; j < 8; j++)
                    acc[i][j] += a[i] * b[j];
        }
        __syncthreads();
        Aptr += 8;
        Bptr += (size_t)8 * N;
    }

    float* Cptr = C + (size_t)(blockIdx.y * 128 + ty * 8) * N + blockIdx.x * 128 + tx * 8;
#pragma unroll
    for (int i = 0; i < 8; i++) {
        *(float4*)(Cptr + (size_t)i * N) =
            make_float4(acc[i][0], acc[i][1], acc[i][2], acc[i][3]);
        *(float4*)(Cptr + (size_t)i * N + 4) =
            make_float4(acc[i][4], acc[i][5], acc[i][6], acc[i][7]);
    }
}

// ---------------------------------------------------------------------------
// RoPE in-place on [b,s,nheads,64]: each thread handles one (row, d<32) pair.
// new_lo = lo*cos[d]    - hi*sin[d]
// new_hi = hi*cos[d+32] + lo*sin[d+32]
// ---------------------------------------------------------------------------
__global__ void rope_kernel(float* __restrict__ p, int nheads, int total,
                            const float* __restrict__ cs, const float* __restrict__ sn)
{
    int idx = blockIdx.x * blockDim.x + threadIdx.x;
    if (idx >= total) return;
    int d = idx & 31;
    int rest = idx >> 5;                       // (b*SEQ+s)*nheads + h
    int s = (rest / nheads) % SEQ;
    size_t base = (size_t)rest * HD;
    float lo = p[base + d], hi = p[base + d + 32];
    float c0 = cs[s * HD + d],      s0 = sn[s * HD + d];
    float c1 = cs[s * HD + d + 32], s1 = sn[s * HD + d + 32];
    p[base + d]      = lo * c0 - hi * s0;
    p[base + d + 32] = hi * c1 + lo * s1;
}

// ---------------------------------------------------------------------------
// Flash attention, fp32. Block handles (b, h, 64-row Q tile). 256 threads as
// 16x16; each thread owns a 4x4 fragment. K stored d-major (transposed) in
// smem so score-GEMM LDS.128 is conflict-free; V row-major so PV is too.
// Online softmax state (m,l) replicated across the 16 lanes of each row group.
// ---------------------------------------------------------------------------
__global__ __launch_bounds__(256) void attn_kernel(
    const float* __restrict__ Qg, const float* __restrict__ Kg,
    const float* __restrict__ Vg, float* __restrict__ Og)
{
    extern __shared__ float smem[];
    float* Qs  = smem;           // [64][64] row-major (row=q, col=d)
    float* Kst = smem + 4096;    // [64][64] d-major   (row=d, col=k)
    float* Vs  = smem + 8192;    // [64][64] row-major (row=k, col=d)
    float* Ss  = smem + 12288;   // [64][64] P tile

    const int qb = blockIdx.x, h = blockIdx.y, b = blockIdx.z;
    const int kvh = h >> 2;      // 4 Q heads per KV head
    const int tid = threadIdx.x;
    const int tx = tid & 15, ty = tid >> 4;
    const int tx4 = tx * 4, ty4 = ty * 4;

    // Load Q tile
    for (int i = tid; i < 64 * 16; i += 256) {
        int r = i >> 4;
        int c4 = (i & 15) << 2;
        *(float4*)&Qs[r * 64 + c4] =
            *(const float4*)&Qg[(((size_t)b * SEQ + qb * 64 + r) * NH + h) * HD + c4];
    }

    float m_i[4], l_i[4], o[4][4];
#pragma unroll
    for (int i = 0; i < 4; i++) {
        m_i[i] = -1e30f; l_i[i] = 0.f;
#pragma unroll
        for (int j = 0; j < 4; j++) o[i][j] = 0.f;
    }

    for (int kb = 0; kb <= qb; kb++) {
        __syncthreads();   // Qs ready (first iter) / previous PV done
        // Load K (transposed) + V
        for (int i = tid; i < 64 * 16; i += 256) {
            int r = i >> 4;
            int c4 = (i & 15) << 2;
            size_t base = (((size_t)b * SEQ + kb * 64 + r) * NKV + kvh) * HD + c4;
            float4 kv = *(const float4*)&Kg[base];
            Kst[(c4 + 0) * 64 + r] = kv.x;
            Kst[(c4 + 1) * 64 + r] = kv.y;
            Kst[(c4 + 2) * 64 + r] = kv.z;
            Kst[(c4 + 3) * 64 + r] = kv.w;
            *(float4*)&Vs[r * 64 + c4] = *(const float4*)&Vg[base];
        }
        __syncthreads();

        // S = Q @ K^T (4x4 fragment per thread)
        float s[4][4];
#pragma unroll
        for (int i = 0; i < 4; i++)
#pragma unroll
            for (int j = 0; j < 4; j++) s[i][j] = 0.f;

#pragma unroll
        for (int d4 = 0; d4 < 64; d4 += 4) {
            float qf[4][4], kf[4][4];
#pragma unroll
            for (int i = 0; i < 4; i++)
                *(float4*)qf[i] = *(const float4*)&Qs[(ty4 + i) * 64 + d4];
#pragma unroll
            for (int t = 0; t < 4; t++)
                *(float4*)kf[t] = *(const float4*)&Kst[(d4 + t) * 64 + tx4];
#pragma unroll
            for (int i = 0; i < 4; i++)
#pragma unroll
                for (int j = 0; j < 4; j++)
                    s[i][j] += qf[i][0] * kf[0][j] + qf[i][1] * kf[1][j]
                             + qf[i][2] * kf[2][j] + qf[i][3] * kf[3][j];
        }

        // scale + causal mask (only diagonal tile needs it)
#pragma unroll
        for (int i = 0; i < 4; i++)
#pragma unroll
            for (int j = 0; j < 4; j++) {
                s[i][j] *= ATT_SCALE;
                if (kb == qb && (tx4 + j) > (ty4 + i)) s[i][j] = -1e30f;
            }

        // Online softmax; rows live across the 16-lane tx group of this warp.
#pragma unroll
        for (int i = 0; i < 4; i++) {
            float rm = fmaxf(fmaxf(s[i][0], s[i][1]), fmaxf(s[i][2], s[i][3]));
#pragma unroll
            for (int off = 1; off < 16; off <<= 1)
                rm = fmaxf(rm, __shfl_xor_sync(0xffffffffu, rm, off));
            float mn = fmaxf(m_i[i], rm);
            float alpha = __expf(m_i[i] - mn);
            float ps = 0.f;
#pragma unroll
            for (int j = 0; j < 4; j++) {
                s[i][j] = __expf(s[i][j] - mn);
                ps += s[i][j];
            }
#pragma unroll
            for (int off = 1; off < 16; off <<= 1)
                ps += __shfl_xor_sync(0xffffffffu, ps, off);
            l_i[i] = l_i[i] * alpha + ps;
            m_i[i] = mn;
#pragma unroll
            for (int j = 0; j < 4; j++) o[i][j] *= alpha;
        }

        // Stage P
#pragma unroll
        for (int i = 0; i < 4; i++)
            *(float4*)&Ss[(ty4 + i) * 64 + tx4] =
                make_float4(s[i][0], s[i][1], s[i][2], s[i][3]);
        __syncthreads();

        // O += P @ V
#pragma unroll
        for (int c4 = 0; c4 < 64; c4 += 4) {
            float pf[4][4], vf[4][4];
#pragma unroll
            for (int i = 0; i < 4; i++)
                *(float4*)pf[i] = *(const float4*)&Ss[(ty4 + i) * 64 + c4];
#pragma unroll
            for (int t = 0; t < 4; t++)
                *(float4*)vf[t] = *(const float4*)&Vs[(c4 + t) * 64 + tx4];
#pragma unroll
            for (int i = 0; i < 4; i++)
#pragma unroll
                for (int j = 0; j < 4; j++)
                    o[i][j] += pf[i][0] * vf[0][j] + pf[i][1] * vf[1][j]
                             + pf[i][2] * vf[2][j] + pf[i][3] * vf[3][j];
        }
    }

    // Epilogue: normalize and write [b,s,h,d]
#pragma unroll
    for (int i = 0; i < 4; i++) {
        float inv = 1.f / l_i[i];
        size_t base = (((size_t)b * SEQ + qb * 64 + ty4 + i) * NH + h) * HD + tx4;
        *(float4*)&Og[base] =
            make_float4(o[i][0] * inv, o[i][1] * inv, o[i][2] * inv, o[i][3] * inv);
    }
}

// ---------------------------------------------------------------------------
extern "C" void kernel_launch(void* const* d_in, const int* in_sizes, int n_in,
                              void* d_out, int out_size)
{
    const float* x  = (const float*)d_in[0];
    const float* Wq = (const float*)d_in[1];
    const float* Wk = (const float*)d_in[2];
    const float* Wv = (const float*)d_in[3];
    const float* Wo = (const float*)d_in[4];
    const float* cs = (const float*)d_in[5];
    const float* sn = (const float*)d_in[6];
    // d_in[7] = attention_mask (pure causal; reproduced analytically)
    float* out = (float*)d_out;

    float *q, *k, *v, *o;
    cudaGetSymbolAddress((void**)&q, g_q);
    cudaGetSymbolAddress((void**)&k, g_k);
    cudaGetSymbolAddress((void**)&v, g_v);
    cudaGetSymbolAddress((void**)&o, g_o);

    cudaFuncSetAttribute(attn_kernel, cudaFuncAttributeMaxDynamicSharedMemorySize, 65536);

    const int M = BATCH * SEQ;  // 4096

    sgemm128<<<dim3(DIM / 128, M / 128), 256>>>(x, Wq, q, M, NH * HD, DIM);
    sgemm128<<<dim3((NKV * HD) / 128, M / 128), 256>>>(x, Wk, k, M, NKV * HD, DIM);
    sgemm128<<<dim3((NKV * HD) / 128, M / 128), 256>>>(x, Wv, v, M, NKV * HD, DIM);

    const int qtot = BATCH * SEQ * NH * 32;
    const int ktot = BATCH * SEQ * NKV * 32;
    rope_kernel<<<(qtot + 255) / 256, 256>>>(q, NH, qtot, cs, sn);
    rope_kernel<<<(ktot + 255) / 256, 256>>>(k, NKV, ktot, cs, sn);

    attn_kernel<<<dim3(SEQ / 64, NH, BATCH), 256, 65536>>>(q, k, v, o);

    sgemm128<<<dim3(DIM / 128, M / 128), 256>>>(o, Wo, out, M, DIM, DIM);
}

// round 2
// speedup vs baseline: 2.8041x; 2.8041x over previous
#include <cuda_runtime.h>
#include <cuda_bf16.h>
#include <cstdint>

#define BATCH 2
#define SEQ 2048
#define DIM 2048
#define NH 32
#define NKV 8
#define HD 64
#define ATT_SCALE 0.125f

// Scratch (no cudaMalloc allowed)
__device__ float g_q[BATCH * SEQ * NH * HD];    // [b,s,h,d]
__device__ float g_k[BATCH * SEQ * NKV * HD];   // [b,s,kh,d]
__device__ float g_v[BATCH * SEQ * NKV * HD];   // [b,s,kh,d]
__device__ float g_o[BATCH * SEQ * NH * HD];    // [b,s,h,d]

// ---------------------------------------------------------------------------
// helpers
// ---------------------------------------------------------------------------
__device__ __forceinline__ float tf32r(float x) {
    uint32_t r;
    asm("cvt.rna.tf32.f32 %0, %1;" : "=r"(r) : "f"(x));
    return __uint_as_float(r);
}

__device__ __forceinline__ void mma_tf32(float c[4],
                                         uint32_t a0, uint32_t a1, uint32_t a2, uint32_t a3,
                                         uint32_t b0, uint32_t b1) {
    asm volatile(
        "mma.sync.aligned.m16n8k8.row.col.f32.tf32.tf32.f32 "
        "{%0,%1,%2,%3}, {%4,%5,%6,%7}, {%8,%9}, {%0,%1,%2,%3};"
        : "+f"(c[0]), "+f"(c[1]), "+f"(c[2]), "+f"(c[3])
        : "r"(a0), "r"(a1), "r"(a2), "r"(a3), "r"(b0), "r"(b1));
}

// ---------------------------------------------------------------------------
// tf32 GEMM: C[M,N] = A[M,K] @ B[K,N], all row-major fp32.
// 128x128 tile, BK=16, 256 threads = 8 warps (2 m x 4 n), warp tile 64x32.
// ---------------------------------------------------------------------------
#define GLDA 20    // As row stride (words): banks 20g+t conflict-free
#define GLDB 136   // Bs row stride (words): banks 8t+g conflict-free

__global__ __launch_bounds__(256) void tgemm(
    const float* __restrict__ A, const float* __restrict__ B,
    float* __restrict__ C, int M, int N, int K)
{
    __shared__ float As[2][128 * GLDA];
    __shared__ float Bs[2][16 * GLDB];

    const int tid = threadIdx.x;
    const int warp = tid >> 5, lane = tid & 31;
    const int g = lane >> 2, t = lane & 3;
    const int wm = warp & 1, wn = warp >> 1;   // 2 x 4 warp grid

    const int arow = tid >> 1, akq = (tid & 1) * 8;
    const int brow = tid >> 4, bcol = (tid & 15) * 8;

    const float* Ag = A + (size_t)(blockIdx.y * 128 + arow) * K + akq;
    const float* Bg = B + (size_t)brow * N + blockIdx.x * 128 + bcol;

    float acc[4][4][4];
#pragma unroll
    for (int i = 0; i < 4; i++)
#pragma unroll
        for (int j = 0; j < 4; j++)
#pragma unroll
            for (int c = 0; c < 4; c++) acc[i][j][c] = 0.f;

    const int KT = K / 16;
    float4 ar0, ar1, br0, br1;

    // prologue: load tile 0
    ar0 = *(const float4*)(Ag);
    ar1 = *(const float4*)(Ag + 4);
    br0 = *(const float4*)(Bg);
    br1 = *(const float4*)(Bg + 4);

    {
        float* as = &As[0][arow * GLDA + akq];
        as[0] = tf32r(ar0.x); as[1] = tf32r(ar0.y); as[2] = tf32r(ar0.z); as[3] = tf32r(ar0.w);
        as[4] = tf32r(ar1.x); as[5] = tf32r(ar1.y); as[6] = tf32r(ar1.z); as[7] = tf32r(ar1.w);
        float* bs = &Bs[0][brow * GLDB + bcol];
        bs[0] = tf32r(br0.x); bs[1] = tf32r(br0.y); bs[2] = tf32r(br0.z); bs[3] = tf32r(br0.w);
        bs[4] = tf32r(br1.x); bs[5] = tf32r(br1.y); bs[6] = tf32r(br1.z); bs[7] = tf32r(br1.w);
    }
    __syncthreads();

    for (int kt = 0; kt < KT; kt++) {
        const int cur = kt & 1;
        // prefetch next tile into regs
        if (kt + 1 < KT) {
            ar0 = *(const float4*)(Ag + (kt + 1) * 16);
            ar1 = *(const float4*)(Ag + (kt + 1) * 16 + 4);
            br0 = *(const float4*)(Bg + (size_t)(kt + 1) * 16 * N);
            br1 = *(const float4*)(Bg + (size_t)(kt + 1) * 16 * N + 4);
        }
        // compute on cur buffer
        const float* as = As[cur];
        const float* bs = Bs[cur];
#pragma unroll
        for (int ks = 0; ks < 2; ks++) {
            const int k0 = ks * 8;
            uint32_t af[4][4];
#pragma unroll
            for (int mt = 0; mt < 4; mt++) {
                const int m0 = wm * 64 + mt * 16;
                af[mt][0] = __float_as_uint(as[(m0 + g)     * GLDA + k0 + t]);
                af[mt][1] = __float_as_uint(as[(m0 + g + 8) * GLDA + k0 + t]);
                af[mt][2] = __float_as_uint(as[(m0 + g)     * GLDA + k0 + t + 4]);
                af[mt][3] = __float_as_uint(as[(m0 + g + 8) * GLDA + k0 + t + 4]);
            }
#pragma unroll
            for (int nt = 0; nt < 4; nt++) {
                const int n0 = wn * 32 + nt * 8;
                uint32_t b0 = __float_as_uint(bs[(k0 + t)     * GLDB + n0 + g]);
                uint32_t b1 = __float_as_uint(bs[(k0 + t + 4) * GLDB + n0 + g]);
#pragma unroll
                for (int mt = 0; mt < 4; mt++)
                    mma_tf32(acc[mt][nt], af[mt][0], af[mt][1], af[mt][2], af[mt][3], b0, b1);
            }
        }
        // stage next tile to the other buffer
        if (kt + 1 < KT) {
            const int nxt = cur ^ 1;
            float* asd = &As[nxt][arow * GLDA + akq];
            asd[0] = tf32r(ar0.x); asd[1] = tf32r(ar0.y); asd[2] = tf32r(ar0.z); asd[3] = tf32r(ar0.w);
            asd[4] = tf32r(ar1.x); asd[5] = tf32r(ar1.y); asd[6] = tf32r(ar1.z); asd[7] = tf32r(ar1.w);
            float* bsd = &Bs[nxt][brow * GLDB + bcol];
            bsd[0] = tf32r(br0.x); bsd[1] = tf32r(br0.y); bsd[2] = tf32r(br0.z); bsd[3] = tf32r(br0.w);
            bsd[4] = tf32r(br1.x); bsd[5] = tf32r(br1.y); bsd[6] = tf32r(br1.z); bsd[7] = tf32r(br1.w);
        }
        __syncthreads();
    }

    // epilogue
#pragma unroll
    for (int mt = 0; mt < 4; mt++) {
        const int row = blockIdx.y * 128 + wm * 64 + mt * 16 + g;
#pragma unroll
        for (int nt = 0; nt < 4; nt++) {
            const int col = blockIdx.x * 128 + wn * 32 + nt * 8 + 2 * t;
            *(float2*)&C[(size_t)row * N + col] = make_float2(acc[mt][nt][0], acc[mt][nt][1]);
            *(float2*)&C[(size_t)(row + 8) * N + col] = make_float2(acc[mt][nt][2], acc[mt][nt][3]);
        }
    }
}

// ---------------------------------------------------------------------------
// RoPE in-place on [b,s,nheads,64]
// ---------------------------------------------------------------------------
__global__ void rope_kernel(float* __restrict__ p, int nheads, int total,
                            const float* __restrict__ cs, const float* __restrict__ sn)
{
    int idx = blockIdx.x * blockDim.x + threadIdx.x;
    if (idx >= total) return;
    int d = idx & 31;
    int rest = idx >> 5;
    int s = (rest / nheads) % SEQ;
    size_t base = (size_t)rest * HD;
    float lo = p[base + d], hi = p[base + d + 32];
    float c0 = cs[s * HD + d],      s0 = sn[s * HD + d];
    float c1 = cs[s * HD + d + 32], s1 = sn[s * HD + d + 32];
    p[base + d]      = lo * c0 - hi * s0;
    p[base + d + 32] = hi * c1 + lo * s1;
}

// ---------------------------------------------------------------------------
// tf32 flash attention. Block = (qb of 128 rows, h, b). 256 threads = 8 warps,
// warp w owns q rows [w*16, w*16+16). KV chunks of 64.
//   Qs[128][68]  (q row-major, pre-scaled, tf32)   A-frag banks 4g+t OK
//   Kst[64][72]  (d-major)                          B-frag banks 8t+g OK
//   Vs[64][72]   (kv row-major)                     B-frag banks 8t+g OK
//   Ps[128][68]  (P staging, warp-private rows)     A-frag banks 4g+t OK
// ---------------------------------------------------------------------------
#define QLD 68
#define KLD 72

__global__ __launch_bounds__(256) void attn_mma(
    const float* __restrict__ Qg, const float* __restrict__ Kg,
    const float* __restrict__ Vg, float* __restrict__ Og)
{
    extern __shared__ float smem[];
    float* Qs  = smem;                       // 128*68 = 8704
    float* Kst = Qs + 128 * QLD;             // 64*72  = 4608
    float* Vs  = Kst + 64 * KLD;             // 64*72  = 4608
    float* Ps  = Vs + 64 * KLD;              // 128*68 = 8704

    const int qb = blockIdx.x, h = blockIdx.y, b = blockIdx.z;
    const int kvh = h >> 2;
    const int tid = threadIdx.x;
    const int warp = tid >> 5, lane = tid & 31;
    const int g = lane >> 2, t = lane & 3;
    const int rowbase = warp * 16;           // warp-local q row base inside tile

    // ---- load Q (pre-scaled, tf32) ----
    {
        const int row = tid >> 1;
        const int dbase = (tid & 1) * 32;
        const float* src = &Qg[(((size_t)b * SEQ + qb * 128 + row) * NH + h) * HD + dbase];
        float* dst = &Qs[row * QLD + dbase];
#pragma unroll
        for (int i = 0; i < 8; i++) {
            float4 v = *(const float4*)(src + 4 * i);
            dst[4 * i + 0] = tf32r(v.x * ATT_SCALE);
            dst[4 * i + 1] = tf32r(v.y * ATT_SCALE);
            dst[4 * i + 2] = tf32r(v.z * ATT_SCALE);
            dst[4 * i + 3] = tf32r(v.w * ATT_SCALE);
        }
    }

    float m0r = -1e30f, m1r = -1e30f, l0r = 0.f, l1r = 0.f;
    float of[8][4];
#pragma unroll
    for (int nt = 0; nt < 8; nt++)
#pragma unroll
        for (int c = 0; c < 4; c++) of[nt][c] = 0.f;

    const int nchunks = 2 * (qb + 1);
    const int kvrow = tid >> 2;
    const int dld   = (tid & 3) * 16;

    for (int kc = 0; kc < nchunks; kc++) {
        __syncthreads();   // prev compute done (and Q visible on first iter)
        // ---- load K (transposed) + V chunk ----
        {
            const size_t gbase = (((size_t)b * SEQ + kc * 64 + kvrow) * NKV + kvh) * HD + dld;
            const float* ksrc = &Kg[gbase];
            const float* vsrc = &Vg[gbase];
#pragma unroll
            for (int i = 0; i < 4; i++) {
                float4 kv4 = *(const float4*)(ksrc + 4 * i);
                Kst[(dld + 4 * i + 0) * KLD + kvrow] = tf32r(kv4.x);
                Kst[(dld + 4 * i + 1) * KLD + kvrow] = tf32r(kv4.y);
                Kst[(dld + 4 * i + 2) * KLD + kvrow] = tf32r(kv4.z);
                Kst[(dld + 4 * i + 3) * KLD + kvrow] = tf32r(kv4.w);
                float4 vv = *(const float4*)(vsrc + 4 * i);
                float* vd = &Vs[kvrow * KLD + dld + 4 * i];
                vd[0] = tf32r(vv.x); vd[1] = tf32r(vv.y);
                vd[2] = tf32r(vv.z); vd[3] = tf32r(vv.w);
            }
        }
        __syncthreads();

        // ---- S = Q K^T ----
        float sf[8][4];
#pragma unroll
        for (int nt = 0; nt < 8; nt++)
#pragma unroll
            for (int c = 0; c < 4; c++) sf[nt][c] = 0.f;

#pragma unroll
        for (int kt = 0; kt < 8; kt++) {
            const int k0 = kt * 8;
            uint32_t a0 = __float_as_uint(Qs[(rowbase + g)     * QLD + k0 + t]);
            uint32_t a1 = __float_as_uint(Qs[(rowbase + g + 8) * QLD + k0 + t]);
            uint32_t a2 = __float_as_uint(Qs[(rowbase + g)     * QLD + k0 + t + 4]);
            uint32_t a3 = __float_as_uint(Qs[(rowbase + g + 8) * QLD + k0 + t + 4]);
#pragma unroll
            for (int nt = 0; nt < 8; nt++) {
                uint32_t b0 = __float_as_uint(Kst[(k0 + t)     * KLD + nt * 8 + g]);
                uint32_t b1 = __float_as_uint(Kst[(k0 + t + 4) * KLD + nt * 8 + g]);
                mma_tf32(sf[nt], a0, a1, a2, a3, b0, b1);
            }
        }

        // ---- causal mask (only when chunk can cross diagonal for this warp) ----
        const int qr0 = qb * 128 + rowbase + g;
        const int qr1 = qr0 + 8;
        if (kc * 64 + 63 > qr0) {
#pragma unroll
            for (int nt = 0; nt < 8; nt++) {
                const int kv0 = kc * 64 + nt * 8 + 2 * t;
                if (kv0 > qr0)     sf[nt][0] = -1e30f;
                if (kv0 + 1 > qr0) sf[nt][1] = -1e30f;
                if (kv0 > qr1)     sf[nt][2] = -1e30f;
                if (kv0 + 1 > qr1) sf[nt][3] = -1e30f;
            }
        }

        // ---- online softmax (rows g and g+8; replicated over quad lanes) ----
        float mx0 = -1e30f, mx1 = -1e30f;
#pragma unroll
        for (int nt = 0; nt < 8; nt++) {
            mx0 = fmaxf(mx0, fmaxf(sf[nt][0], sf[nt][1]));
            mx1 = fmaxf(mx1, fmaxf(sf[nt][2], sf[nt][3]));
        }
        mx0 = fmaxf(mx0, __shfl_xor_sync(0xffffffffu, mx0, 1));
        mx0 = fmaxf(mx0, __shfl_xor_sync(0xffffffffu, mx0, 2));
        mx1 = fmaxf(mx1, __shfl_xor_sync(0xffffffffu, mx1, 1));
        mx1 = fmaxf(mx1, __shfl_xor_sync(0xffffffffu, mx1, 2));

        const float mn0 = fmaxf(m0r, mx0);
        const float mn1 = fmaxf(m1r, mx1);
        const float al0 = __expf(m0r - mn0);
        const float al1 = __expf(m1r - mn1);
        m0r = mn0; m1r = mn1;

        float ps0 = 0.f, ps1 = 0.f;
#pragma unroll
        for (int nt = 0; nt < 8; nt++) {
            sf[nt][0] = __expf(sf[nt][0] - mn0);
            sf[nt][1] = __expf(sf[nt][1] - mn0);
            sf[nt][2] = __expf(sf[nt][2] - mn1);
            sf[nt][3] = __expf(sf[nt][3] - mn1);
            ps0 += sf[nt][0] + sf[nt][1];
            ps1 += sf[nt][2] + sf[nt][3];
        }
        ps0 += __shfl_xor_sync(0xffffffffu, ps0, 1);
        ps0 += __shfl_xor_sync(0xffffffffu, ps0, 2);
        ps1 += __shfl_xor_sync(0xffffffffu, ps1, 1);
        ps1 += __shfl_xor_sync(0xffffffffu, ps1, 2);
        l0r = l0r * al0 + ps0;
        l1r = l1r * al1 + ps1;

#pragma unroll
        for (int nt = 0; nt < 8; nt++) {
            of[nt][0] *= al0; of[nt][1] *= al0;
            of[nt][2] *= al1; of[nt][3] *= al1;
        }

        // ---- stage P (tf32) to warp-private Ps rows ----
#pragma unroll
        for (int nt = 0; nt < 8; nt++) {
            float* p0 = &Ps[(rowbase + g) * QLD + nt * 8 + 2 * t];
            p0[0] = tf32r(sf[nt][0]); p0[1] = tf32r(sf[nt][1]);
            float* p1 = &Ps[(rowbase + g + 8) * QLD + nt * 8 + 2 * t];
            p1[0] = tf32r(sf[nt][2]); p1[1] = tf32r(sf[nt][3]);
        }
        __syncwarp();

        // ---- O += P @ V ----
#pragma unroll
        for (int kt = 0; kt < 8; kt++) {
            const int k0 = kt * 8;
            uint32_t a0 = __float_as_uint(Ps[(rowbase + g)     * QLD + k0 + t]);
            uint32_t a1 = __float_as_uint(Ps[(rowbase + g + 8) * QLD + k0 + t]);
            uint32_t a2 = __float_as_uint(Ps[(rowbase + g)     * QLD + k0 + t + 4]);
            uint32_t a3 = __float_as_uint(Ps[(rowbase + g + 8) * QLD + k0 + t + 4]);
#pragma unroll
            for (int nt = 0; nt < 8; nt++) {
                uint32_t b0 = __float_as_uint(Vs[(k0 + t)     * KLD + nt * 8 + g]);
                uint32_t b1 = __float_as_uint(Vs[(k0 + t + 4) * KLD + nt * 8 + g]);
                mma_tf32(of[nt], a0, a1, a2, a3, b0, b1);
            }
        }
        __syncwarp();   // Ps reads done before next chunk overwrites
    }

    // ---- epilogue ----
    const float inv0 = 1.f / l0r, inv1 = 1.f / l1r;
    const int row0 = qb * 128 + rowbase + g;
#pragma unroll
    for (int nt = 0; nt < 8; nt++) {
        const int col = nt * 8 + 2 * t;
        *(float2*)&Og[(((size_t)b * SEQ + row0) * NH + h) * HD + col] =
            make_float2(of[nt][0] * inv0, of[nt][1] * inv0);
        *(float2*)&Og[(((size_t)b * SEQ + row0 + 8) * NH + h) * HD + col] =
            make_float2(of[nt][2] * inv1, of[nt][3] * inv1);
    }
}

// ---------------------------------------------------------------------------
extern "C" void kernel_launch(void* const* d_in, const int* in_sizes, int n_in,
                              void* d_out, int out_size)
{
    const float* x  = (const float*)d_in[0];
    const float* Wq = (const float*)d_in[1];
    const float* Wk = (const float*)d_in[2];
    const float* Wv = (const float*)d_in[3];
    const float* Wo = (const float*)d_in[4];
    const float* cs = (const float*)d_in[5];
    const float* sn = (const float*)d_in[6];
    float* out = (float*)d_out;

    float *q, *k, *v, *o;
    cudaGetSymbolAddress((void**)&q, g_q);
    cudaGetSymbolAddress((void**)&k, g_k);
    cudaGetSymbolAddress((void**)&v, g_v);
    cudaGetSymbolAddress((void**)&o, g_o);

    const int ATTN_SMEM = (128 * QLD + 64 * KLD * 2 + 128 * QLD) * 4;  // 106496 B
    cudaFuncSetAttribute(attn_mma, cudaFuncAttributeMaxDynamicSharedMemorySize, ATTN_SMEM);

    const int M = BATCH * SEQ;  // 4096

    tgemm<<<dim3(DIM / 128, M / 128), 256>>>(x, Wq, q, M, NH * HD, DIM);
    tgemm<<<dim3((NKV * HD) / 128, M / 128), 256>>>(x, Wk, k, M, NKV * HD, DIM);
    tgemm<<<dim3((NKV * HD) / 128, M / 128), 256>>>(x, Wv, v, M, NKV * HD, DIM);

    const int qtot = BATCH * SEQ * NH * 32;
    const int ktot = BATCH * SEQ * NKV * 32;
    rope_kernel<<<(qtot + 255) / 256, 256>>>(q, NH, qtot, cs, sn);
    rope_kernel<<<(ktot + 255) / 256, 256>>>(k, NKV, ktot, cs, sn);

    attn_mma<<<dim3(SEQ / 128, NH, BATCH), 256, ATTN_SMEM>>>(q, k, v, o);

    tgemm<<<dim3(DIM / 128, M / 128), 256>>>(o, Wo, out, M, DIM, DIM);
}

// round 5
// speedup vs baseline: 5.8419x; 2.0833x over previous
#include <cuda_runtime.h>
#include <cuda_fp16.h>
#include <cstdint>

#define BATCH 2
#define SEQ 2048
#define DIM 2048
#define NH 32
#define NKV 8
#define HD 64
#define ATT_SCALE 0.125f
#define MTOT (BATCH * SEQ)

extern __shared__ char dsmem[];

// Scratch (no cudaMalloc allowed)
__device__ float  g_qf[MTOT * NH * HD];       // fp32 q pre-rope
__device__ float  g_kf[MTOT * NKV * HD];      // fp32 k pre-rope
__device__ __half g_xh[MTOT * DIM];
__device__ __half g_qh[MTOT * NH * HD];
__device__ __half g_kh[MTOT * NKV * HD];
__device__ __half g_vh[MTOT * NKV * HD];
__device__ __half g_oh[MTOT * NH * HD];
__device__ __half g_wqt[DIM * DIM];           // [N][K] half
__device__ __half g_wkt[NKV * HD * DIM];
__device__ __half g_wvt[NKV * HD * DIM];
__device__ __half g_wot[DIM * DIM];

// ---------------------------------------------------------------------------
// helpers
// ---------------------------------------------------------------------------
__device__ __forceinline__ uint32_t smem_u32(const void* p) {
    uint32_t a;
    asm("{ .reg .u64 t; cvta.to.shared.u64 t, %1; cvt.u32.u64 %0, t; }" : "=r"(a) : "l"(p));
    return a;
}

__device__ __forceinline__ void ldm_x4(uint32_t r[4], uint32_t addr) {
    asm volatile("ldmatrix.sync.aligned.m8n8.x4.shared.b16 {%0,%1,%2,%3}, [%4];"
                 : "=r"(r[0]), "=r"(r[1]), "=r"(r[2]), "=r"(r[3]) : "r"(addr));
}

__device__ __forceinline__ void ldm_x4t(uint32_t r[4], uint32_t addr) {
    asm volatile("ldmatrix.sync.aligned.m8n8.x4.trans.shared.b16 {%0,%1,%2,%3}, [%4];"
                 : "=r"(r[0]), "=r"(r[1]), "=r"(r[2]), "=r"(r[3]) : "r"(addr));
}

__device__ __forceinline__ void mma_f16(float c[4], const uint32_t a[4],
                                        uint32_t b0, uint32_t b1) {
    asm volatile(
        "mma.sync.aligned.m16n8k16.row.col.f32.f16.f16.f32 "
        "{%0,%1,%2,%3}, {%4,%5,%6,%7}, {%8,%9}, {%0,%1,%2,%3};"
        : "+f"(c[0]), "+f"(c[1]), "+f"(c[2]), "+f"(c[3])
        : "r"(a[0]), "r"(a[1]), "r"(a[2]), "r"(a[3]), "r"(b0), "r"(b1));
}

__device__ __forceinline__ void store2(float* C, size_t off, float x, float y) {
    *(float2*)&C[off] = make_float2(x, y);
}
__device__ __forceinline__ void store2(__half* C, size_t off, float x, float y) {
    *(__half2*)&C[off] = __floats2half2_rn(x, y);
}

// ---------------------------------------------------------------------------
// fp32 -> fp16 elementwise
// ---------------------------------------------------------------------------
__global__ void f2h_kernel(const float* __restrict__ in, __half* __restrict__ out, int n)
{
    int i = (blockIdx.x * blockDim.x + threadIdx.x) * 4;
    if (i < n) {
        float4 v = *(const float4*)&in[i];
        *(__half2*)&out[i]     = __floats2half2_rn(v.x, v.y);
        *(__half2*)&out[i + 2] = __floats2half2_rn(v.z, v.w);
    }
}

// ---------------------------------------------------------------------------
// Weight transpose + half convert: in fp32 [K][N] -> out half [N][K]
// ---------------------------------------------------------------------------
__global__ __launch_bounds__(256) void transpose_h(
    const float* __restrict__ in, __half* __restrict__ out, int K, int N)
{
    __shared__ float t[32][33];
    const int k0 = blockIdx.y * 32, n0 = blockIdx.x * 32;
    const int tx = threadIdx.x, ty = threadIdx.y;  // 32 x 8
#pragma unroll
    for (int r = ty; r < 32; r += 8)
        t[r][tx] = in[(size_t)(k0 + r) * N + n0 + tx];
    __syncthreads();
#pragma unroll
    for (int r = ty; r < 32; r += 8)
        out[(size_t)(n0 + r) * K + k0 + tx] = __float2half(t[tx][r]);
}

// ---------------------------------------------------------------------------
// fp16 GEMM: C[M,N] = A[M,K] @ Bt[N,K]^T.  A, Bt half; C float or half.
// 128x128 tile, BK=32, 256 threads = 8 warps (2m x 4n), warp tile 64x32.
// smem rows padded to 40 halves (conflict-free ldmatrix, checked vs bank model).
// ---------------------------------------------------------------------------
#define GPAD 40
#define GBUF (128 * GPAD)              // halves per operand buffer
#define HGEMM_SMEM (4 * GBUF * 2)      // 40960 B

template <typename TO>
__global__ __launch_bounds__(256) void hgemm(
    const __half* __restrict__ A, const __half* __restrict__ Bt,
    TO* __restrict__ C, int M, int N, int K)
{
    __half* Asm = (__half*)dsmem;           // [2][GBUF]
    __half* Bsm = Asm + 2 * GBUF;           // [2][GBUF]
    const uint32_t sA = smem_u32(Asm), sB = smem_u32(Bsm);

    const int tid = threadIdx.x, lane = tid & 31, warp = tid >> 5;
    const int wm = warp & 1, wn = warp >> 1;
    const int g = lane >> 2, t = lane & 3;
    const int srow = tid >> 1, sk = (tid & 1) * 16;

    // ldmatrix lane addressing
    const int ra = (lane & 7) + 8 * ((lane >> 3) & 1);   // A row-in-tile
    const int ca = 8 * (lane >> 4);                      // A col offset
    const int rb = (lane & 7) + 8 * (lane >> 4);         // B row-in-tile
    const int cb = 8 * ((lane >> 3) & 1);                // B col offset

    const __half* Ag = A + (size_t)(blockIdx.y * 128 + srow) * K + sk;
    const __half* Bg = Bt + (size_t)(blockIdx.x * 128 + srow) * K + sk;

    float acc[4][4][4];
#pragma unroll
    for (int i = 0; i < 4; i++)
#pragma unroll
        for (int j = 0; j < 4; j++)
#pragma unroll
            for (int c = 0; c < 4; c++) acc[i][j][c] = 0.f;

    const int KT = K / 32;
    uint4 pa0, pa1, pb0, pb1;
    pa0 = *(const uint4*)Ag;       pa1 = *(const uint4*)(Ag + 8);
    pb0 = *(const uint4*)Bg;       pb1 = *(const uint4*)(Bg + 8);
    {
        uint32_t d = sA + (srow * GPAD + sk) * 2;
        asm volatile("st.shared.v4.b32 [%0], {%1,%2,%3,%4};" :: "r"(d),
                     "r"(pa0.x), "r"(pa0.y), "r"(pa0.z), "r"(pa0.w) : "memory");
        asm volatile("st.shared.v4.b32 [%0], {%1,%2,%3,%4};" :: "r"(d + 16),
                     "r"(pa1.x), "r"(pa1.y), "r"(pa1.z), "r"(pa1.w) : "memory");
        d = sB + (srow * GPAD + sk) * 2;
        asm volatile("st.shared.v4.b32 [%0], {%1,%2,%3,%4};" :: "r"(d),
                     "r"(pb0.x), "r"(pb0.y), "r"(pb0.z), "r"(pb0.w) : "memory");
        asm volatile("st.shared.v4.b32 [%0], {%1,%2,%3,%4};" :: "r"(d + 16),
                     "r"(pb1.x), "r"(pb1.y), "r"(pb1.z), "r"(pb1.w) : "memory");
    }
    __syncthreads();

    for (int it = 0; it < KT; it++) {
        const int cur = it & 1;
        if (it + 1 < KT) {
            pa0 = *(const uint4*)(Ag + (it + 1) * 32);
            pa1 = *(const uint4*)(Ag + (it + 1) * 32 + 8);
            pb0 = *(const uint4*)(Bg + (it + 1) * 32);
            pb1 = *(const uint4*)(Bg + (it + 1) * 32 + 8);
        }
        const uint32_t bA = sA + cur * GBUF * 2;
        const uint32_t bB = sB + cur * GBUF * 2;
#pragma unroll
        for (int ks = 0; ks < 2; ks++) {
            const int k0 = ks * 16;
            uint32_t af[4][4];
#pragma unroll
            for (int mt = 0; mt < 4; mt++)
                ldm_x4(af[mt], bA + ((wm * 64 + mt * 16 + ra) * GPAD + k0 + ca) * 2);
#pragma unroll
            for (int bp = 0; bp < 2; bp++) {
                uint32_t b4[4];
                ldm_x4(b4, bB + ((wn * 32 + bp * 16 + rb) * GPAD + k0 + cb) * 2);
#pragma unroll
                for (int mt = 0; mt < 4; mt++) {
                    mma_f16(acc[mt][2 * bp],     af[mt], b4[0], b4[1]);
                    mma_f16(acc[mt][2 * bp + 1], af[mt], b4[2], b4[3]);
                }
            }
        }
        if (it + 1 < KT) {
            const uint32_t nA = sA + (cur ^ 1) * GBUF * 2;
            const uint32_t nB = sB + (cur ^ 1) * GBUF * 2;
            uint32_t d = nA + (srow * GPAD + sk) * 2;
            asm volatile("st.shared.v4.b32 [%0], {%1,%2,%3,%4};" :: "r"(d),
                         "r"(pa0.x), "r"(pa0.y), "r"(pa0.z), "r"(pa0.w) : "memory");
            asm volatile("st.shared.v4.b32 [%0], {%1,%2,%3,%4};" :: "r"(d + 16),
                         "r"(pa1.x), "r"(pa1.y), "r"(pa1.z), "r"(pa1.w) : "memory");
            d = nB + (srow * GPAD + sk) * 2;
            asm volatile("st.shared.v4.b32 [%0], {%1,%2,%3,%4};" :: "r"(d),
                         "r"(pb0.x), "r"(pb0.y), "r"(pb0.z), "r"(pb0.w) : "memory");
            asm volatile("st.shared.v4.b32 [%0], {%1,%2,%3,%4};" :: "r"(d + 16),
                         "r"(pb1.x), "r"(pb1.y), "r"(pb1.z), "r"(pb1.w) : "memory");
        }
        __syncthreads();
    }

#pragma unroll
    for (int mt = 0; mt < 4; mt++) {
        const int row = blockIdx.y * 128 + wm * 64 + mt * 16 + g;
#pragma unroll
        for (int nt = 0; nt < 4; nt++) {
            const int col = blockIdx.x * 128 + wn * 32 + nt * 8 + 2 * t;
            store2(C, (size_t)row * N + col,       acc[mt][nt][0], acc[mt][nt][1]);
            store2(C, (size_t)(row + 8) * N + col, acc[mt][nt][2], acc[mt][nt][3]);
        }
    }
}

// ---------------------------------------------------------------------------
// RoPE: read fp32 [rows][64], write half (optionally pre-scaled)
// ---------------------------------------------------------------------------
__global__ void rope_h(const float* __restrict__ p, __half* __restrict__ ph,
                       int nheads, int total,
                       const float* __restrict__ cs, const float* __restrict__ sn,
                       float scale)
{
    int idx = blockIdx.x * blockDim.x + threadIdx.x;
    if (idx >= total) return;
    int d = idx & 31;
    int rest = idx >> 5;
    int s = (rest / nheads) % SEQ;
    size_t base = (size_t)rest * HD;
    float lo = p[base + d], hi = p[base + d + 32];
    float c0 = cs[s * HD + d],      s0 = sn[s * HD + d];
    float c1 = cs[s * HD + d + 32], s1 = sn[s * HD + d + 32];
    ph[base + d]      = __float2half((lo * c0 - hi * s0) * scale);
    ph[base + d + 32] = __float2half((hi * c1 + lo * s1) * scale);
}

// ---------------------------------------------------------------------------
// fp16 flash attention. Block = (128 q rows, h, b). 8 warps x 16 rows.
// KV chunks of 64. smem rows padded to 72 halves (conflict-free ldmatrix).
// ---------------------------------------------------------------------------
#define APAD 72
#define ATTN_SMEM ((128 + 64 + 64 + 128) * APAD * 2)   // 55296 B

__global__ __launch_bounds__(256) void attn_h(
    const __half* __restrict__ Qg, const __half* __restrict__ Kg,
    const __half* __restrict__ Vg, __half* __restrict__ Og)
{
    __half* Qs = (__half*)dsmem;           // [128][APAD]
    __half* Ks = Qs + 128 * APAD;          // [64][APAD]  (kv, d)
    __half* Vs = Ks + 64 * APAD;           // [64][APAD]  (kv, d)
    __half* Ps = Vs + 64 * APAD;           // [128][APAD]
    const uint32_t sQ = smem_u32(Qs), sK = smem_u32(Ks),
                   sV = smem_u32(Vs), sP = smem_u32(Ps);

    const int qb = blockIdx.x, h = blockIdx.y, b = blockIdx.z;
    const int kvh = h >> 2;
    const int tid = threadIdx.x;
    const int warp = tid >> 5, lane = tid & 31;
    const int g = lane >> 2, t = lane & 3;
    const int rowbase = warp * 16;

    const int ra = (lane & 7) + 8 * ((lane >> 3) & 1);   // A rows / V(trans) rows
    const int ca = 8 * (lane >> 4);
    const int rb = (lane & 7) + 8 * (lane >> 4);         // B rows (K)
    const int cb = 8 * ((lane >> 3) & 1);

    // ---- load Q tile (half, pre-scaled upstream) ----
    {
        const int row = tid & 127;
        const int c0 = (tid >> 7) * 32;
        const __half* src = &Qg[(((size_t)b * SEQ + qb * 128 + row) * NH + h) * HD + c0];
        uint32_t d = sQ + (row * APAD + c0) * 2;
#pragma unroll
        for (int i = 0; i < 4; i++) {
            uint4 v = *(const uint4*)(src + 8 * i);
            asm volatile("st.shared.v4.b32 [%0], {%1,%2,%3,%4};" :: "r"(d + 16 * i),
                         "r"(v.x), "r"(v.y), "r"(v.z), "r"(v.w) : "memory");
        }
    }
    __syncthreads();

    // Q fragments held in registers for the whole kernel
    uint32_t qf[4][4];
#pragma unroll
    for (int kt = 0; kt < 4; kt++)
        ldm_x4(qf[kt], sQ + ((rowbase + ra) * APAD + kt * 16 + ca) * 2);

    float m0r = -1e30f, m1r = -1e30f, l0r = 0.f, l1r = 0.f;
    float of[8][4];
#pragma unroll
    for (int nt = 0; nt < 8; nt++)
#pragma unroll
        for (int c = 0; c < 4; c++) of[nt][c] = 0.f;

    const int nchunks = 2 * (qb + 1);
    const int svrow = tid >> 2;            // 0..63
    const int svc   = (tid & 3) * 16;      // halves

    for (int kc = 0; kc < nchunks; kc++) {
        __syncthreads();   // prev chunk's K/V reads done
        // ---- stage K, V chunk (half, vectorized, conflict-free) ----
        {
            const size_t gb = (((size_t)b * SEQ + kc * 64 + svrow) * NKV + kvh) * HD + svc;
            uint4 k0 = *(const uint4*)&Kg[gb];
            uint4 k1 = *(const uint4*)&Kg[gb + 8];
            uint4 v0 = *(const uint4*)&Vg[gb];
            uint4 v1 = *(const uint4*)&Vg[gb + 8];
            uint32_t dk = sK + (svrow * APAD + svc) * 2;
            uint32_t dv = sV + (svrow * APAD + svc) * 2;
            asm volatile("st.shared.v4.b32 [%0], {%1,%2,%3,%4};" :: "r"(dk),
                         "r"(k0.x), "r"(k0.y), "r"(k0.z), "r"(k0.w) : "memory");
            asm volatile("st.shared.v4.b32 [%0], {%1,%2,%3,%4};" :: "r"(dk + 16),
                         "r"(k1.x), "r"(k1.y), "r"(k1.z), "r"(k1.w) : "memory");
            asm volatile("st.shared.v4.b32 [%0], {%1,%2,%3,%4};" :: "r"(dv),
                         "r"(v0.x), "r"(v0.y), "r"(v0.z), "r"(v0.w) : "memory");
            asm volatile("st.shared.v4.b32 [%0], {%1,%2,%3,%4};" :: "r"(dv + 16),
                         "r"(v1.x), "r"(v1.y), "r"(v1.z), "r"(v1.w) : "memory");
        }
        __syncthreads();

        // ---- S = Q K^T ----
        float sf[8][4];
#pragma unroll
        for (int nt = 0; nt < 8; nt++)
#pragma unroll
            for (int c = 0; c < 4; c++) sf[nt][c] = 0.f;

#pragma unroll
        for (int kt = 0; kt < 4; kt++) {
#pragma unroll
            for (int bp = 0; bp < 4; bp++) {
                uint32_t b4[4];
                ldm_x4(b4, sK + ((bp * 16 + rb) * APAD + kt * 16 + cb) * 2);
                mma_f16(sf[2 * bp],     qf[kt], b4[0], b4[1]);
                mma_f16(sf[2 * bp + 1], qf[kt], b4[2], b4[3]);
            }
        }

        // ---- causal mask ----
        const int qr0 = qb * 128 + rowbase + g;
        const int qr1 = qr0 + 8;
        if (kc * 64 + 63 > qr0) {
#pragma unroll
            for (int nt = 0; nt < 8; nt++) {
                const int kv0 = kc * 64 + nt * 8 + 2 * t;
                if (kv0 > qr0)     sf[nt][0] = -1e30f;
                if (kv0 + 1 > qr0) sf[nt][1] = -1e30f;
                if (kv0 > qr1)     sf[nt][2] = -1e30f;
                if (kv0 + 1 > qr1) sf[nt][3] = -1e30f;
            }
        }

        // ---- online softmax (fp32) ----
        float mx0 = -1e30f, mx1 = -1e30f;
#pragma unroll
        for (int nt = 0; nt < 8; nt++) {
            mx0 = fmaxf(mx0, fmaxf(sf[nt][0], sf[nt][1]));
            mx1 = fmaxf(mx1, fmaxf(sf[nt][2], sf[nt][3]));
        }
        mx0 = fmaxf(mx0, __shfl_xor_sync(0xffffffffu, mx0, 1));
        mx0 = fmaxf(mx0, __shfl_xor_sync(0xffffffffu, mx0, 2));
        mx1 = fmaxf(mx1, __shfl_xor_sync(0xffffffffu, mx1, 1));
        mx1 = fmaxf(mx1, __shfl_xor_sync(0xffffffffu, mx1, 2));

        const float mn0 = fmaxf(m0r, mx0);
        const float mn1 = fmaxf(m1r, mx1);
        const float al0 = __expf(m0r - mn0);
        const float al1 = __expf(m1r - mn1);
        m0r = mn0; m1r = mn1;

        float ps0 = 0.f, ps1 = 0.f;
#pragma unroll
        for (int nt = 0; nt < 8; nt++) {
            sf[nt][0] = __expf(sf[nt][0] - mn0);
            sf[nt][1] = __expf(sf[nt][1] - mn0);
            sf[nt][2] = __expf(sf[nt][2] - mn1);
            sf[nt][3] = __expf(sf[nt][3] - mn1);
            ps0 += sf[nt][0] + sf[nt][1];
            ps1 += sf[nt][2] + sf[nt][3];
        }
        ps0 += __shfl_xor_sync(0xffffffffu, ps0, 1);
        ps0 += __shfl_xor_sync(0xffffffffu, ps0, 2);
        ps1 += __shfl_xor_sync(0xffffffffu, ps1, 1);
        ps1 += __shfl_xor_sync(0xffffffffu, ps1, 2);
        l0r = l0r * al0 + ps0;
        l1r = l1r * al1 + ps1;

#pragma unroll
        for (int nt = 0; nt < 8; nt++) {
            of[nt][0] *= al0; of[nt][1] *= al0;
            of[nt][2] *= al1; of[nt][3] *= al1;
        }

        // ---- stage P as half (warp-private rows) ----
#pragma unroll
        for (int nt = 0; nt < 8; nt++) {
            *(__half2*)&Ps[(rowbase + g) * APAD + nt * 8 + 2 * t] =
                __floats2half2_rn(sf[nt][0], sf[nt][1]);
            *(__half2*)&Ps[(rowbase + g + 8) * APAD + nt * 8 + 2 * t] =
                __floats2half2_rn(sf[nt][2], sf[nt][3]);
        }
        __syncwarp();

        // ---- O += P @ V ----
#pragma unroll
        for (int kt = 0; kt < 4; kt++) {
            uint32_t pf[4];
            ldm_x4(pf, sP + ((rowbase + ra) * APAD + kt * 16 + ca) * 2);
#pragma unroll
            for (int bp = 0; bp < 4; bp++) {
                uint32_t b4[4];
                ldm_x4t(b4, sV + ((kt * 16 + ra) * APAD + bp * 16 + ca) * 2);
                mma_f16(of[2 * bp],     pf, b4[0], b4[1]);
                mma_f16(of[2 * bp + 1], pf, b4[2], b4[3]);
            }
        }
    }

    // ---- epilogue (half out) ----
    const float inv0 = 1.f / l0r, inv1 = 1.f / l1r;
    const int row0 = qb * 128 + rowbase + g;
#pragma unroll
    for (int nt = 0; nt < 8; nt++) {
        const int col = nt * 8 + 2 * t;
        *(__half2*)&Og[(((size_t)b * SEQ + row0) * NH + h) * HD + col] =
            __floats2half2_rn(of[nt][0] * inv0, of[nt][1] * inv0);
        *(__half2*)&Og[(((size_t)b * SEQ + row0 + 8) * NH + h) * HD + col] =
            __floats2half2_rn(of[nt][2] * inv1, of[nt][3] * inv1);
    }
}

// ---------------------------------------------------------------------------
extern "C" void kernel_launch(void* const* d_in, const int* in_sizes, int n_in,
                              void* d_out, int out_size)
{
    const float* x  = (const float*)d_in[0];
    const float* Wq = (const float*)d_in[1];
    const float* Wk = (const float*)d_in[2];
    const float* Wv = (const float*)d_in[3];
    const float* Wo = (const float*)d_in[4];
    const float* cs = (const float*)d_in[5];
    const float* sn = (const float*)d_in[6];
    float* out = (float*)d_out;

    float *qf, *kf;
    __half *xh, *qh, *kh, *vh, *oh, *wqt, *wkt, *wvt, *wot;
    cudaGetSymbolAddress((void**)&qf, g_qf);
    cudaGetSymbolAddress((void**)&kf, g_kf);
    cudaGetSymbolAddress((void**)&xh, g_xh);
    cudaGetSymbolAddress((void**)&qh, g_qh);
    cudaGetSymbolAddress((void**)&kh, g_kh);
    cudaGetSymbolAddress((void**)&vh, g_vh);
    cudaGetSymbolAddress((void**)&oh, g_oh);
    cudaGetSymbolAddress((void**)&wqt, g_wqt);
    cudaGetSymbolAddress((void**)&wkt, g_wkt);
    cudaGetSymbolAddress((void**)&wvt, g_wvt);
    cudaGetSymbolAddress((void**)&wot, g_wot);

    cudaFuncSetAttribute(attn_h, cudaFuncAttributeMaxDynamicSharedMemorySize, ATTN_SMEM);
    cudaFuncSetAttribute(hgemm<float>, cudaFuncAttributeMaxDynamicSharedMemorySize, HGEMM_SMEM);
    cudaFuncSetAttribute(hgemm<__half>, cudaFuncAttributeMaxDynamicSharedMemorySize, HGEMM_SMEM);

    const int M = MTOT;  // 4096

    // x -> half
    f2h_kernel<<<(M * DIM / 4 + 255) / 256, 256>>>(x, xh, M * DIM);

    // weight transposes (fp32 [K][N] -> half [N][K])
    transpose_h<<<dim3(DIM / 32, DIM / 32), dim3(32, 8)>>>(Wq, wqt, DIM, DIM);
    transpose_h<<<dim3((NKV * HD) / 32, DIM / 32), dim3(32, 8)>>>(Wk, wkt, DIM, NKV * HD);
    transpose_h<<<dim3((NKV * HD) / 32, DIM / 32), dim3(32, 8)>>>(Wv, wvt, DIM, NKV * HD);
    transpose_h<<<dim3(DIM / 32, DIM / 32), dim3(32, 8)>>>(Wo, wot, DIM, DIM);

    // projections
    hgemm<float><<<dim3(DIM / 128, M / 128), 256, HGEMM_SMEM>>>(xh, wqt, qf, M, DIM, DIM);
    hgemm<float><<<dim3((NKV * HD) / 128, M / 128), 256, HGEMM_SMEM>>>(xh, wkt, kf, M, NKV * HD, DIM);
    hgemm<__half><<<dim3((NKV * HD) / 128, M / 128), 256, HGEMM_SMEM>>>(xh, wvt, vh, M, NKV * HD, DIM);

    // rope -> half (q pre-scaled)
    const int qtot = MTOT * NH * 32;
    const int ktot = MTOT * NKV * 32;
    rope_h<<<(qtot + 255) / 256, 256>>>(qf, qh, NH, qtot, cs, sn, ATT_SCALE);
    rope_h<<<(ktot + 255) / 256, 256>>>(kf, kh, NKV, ktot, cs, sn, 1.0f);

    // attention
    attn_h<<<dim3(SEQ / 128, NH, BATCH), 256, ATTN_SMEM>>>(qh, kh, vh, oh);

    // output projection
    hgemm<float><<<dim3(DIM / 128, M / 128), 256, HGEMM_SMEM>>>(oh, wot, out, M, DIM, DIM);
}

// round 6
// speedup vs baseline: 6.5121x; 1.1147x over previous
#include <cuda_runtime.h>
#include <cuda_fp16.h>
#include <cstdint>

#define BATCH 2
#define SEQ 2048
#define DIM 2048
#define NH 32
#define NKV 8
#define HD 64
#define ATT_SCALE 0.125f
#define MTOT (BATCH * SEQ)

extern __shared__ char dsmem[];

// Scratch (no cudaMalloc allowed)
__device__ float  g_qf[MTOT * NH * HD];       // fp32 q pre-rope
__device__ float  g_kf[MTOT * NKV * HD];      // fp32 k pre-rope
__device__ __half g_xh[MTOT * DIM];
__device__ __half g_qh[MTOT * NH * HD];
__device__ __half g_kh[MTOT * NKV * HD];
__device__ __half g_vh[MTOT * NKV * HD];
__device__ __half g_oh[MTOT * NH * HD];
__device__ __half g_wqt[DIM * DIM];           // [N][K] half
__device__ __half g_wkt[NKV * HD * DIM];
__device__ __half g_wvt[NKV * HD * DIM];
__device__ __half g_wot[DIM * DIM];

// ---------------------------------------------------------------------------
// helpers
// ---------------------------------------------------------------------------
__device__ __forceinline__ uint32_t smem_u32(const void* p) {
    uint32_t a;
    asm("{ .reg .u64 t; cvta.to.shared.u64 t, %1; cvt.u32.u64 %0, t; }" : "=r"(a) : "l"(p));
    return a;
}

__device__ __forceinline__ void cpa16(uint32_t dst, const void* src) {
    asm volatile("cp.async.cg.shared.global [%0], [%1], 16;" :: "r"(dst), "l"(src) : "memory");
}
#define CP_COMMIT() asm volatile("cp.async.commit_group;" ::: "memory")
#define CP_WAIT1()  asm volatile("cp.async.wait_group 1;" ::: "memory")

__device__ __forceinline__ void ldm_x4(uint32_t r[4], uint32_t addr) {
    asm volatile("ldmatrix.sync.aligned.m8n8.x4.shared.b16 {%0,%1,%2,%3}, [%4];"
                 : "=r"(r[0]), "=r"(r[1]), "=r"(r[2]), "=r"(r[3]) : "r"(addr));
}

__device__ __forceinline__ void ldm_x4t(uint32_t r[4], uint32_t addr) {
    asm volatile("ldmatrix.sync.aligned.m8n8.x4.trans.shared.b16 {%0,%1,%2,%3}, [%4];"
                 : "=r"(r[0]), "=r"(r[1]), "=r"(r[2]), "=r"(r[3]) : "r"(addr));
}

__device__ __forceinline__ void mma_f16(float c[4], const uint32_t a[4],
                                        uint32_t b0, uint32_t b1) {
    asm volatile(
        "mma.sync.aligned.m16n8k16.row.col.f32.f16.f16.f32 "
        "{%0,%1,%2,%3}, {%4,%5,%6,%7}, {%8,%9}, {%0,%1,%2,%3};"
        : "+f"(c[0]), "+f"(c[1]), "+f"(c[2]), "+f"(c[3])
        : "r"(a[0]), "r"(a[1]), "r"(a[2]), "r"(a[3]), "r"(b0), "r"(b1));
}

__device__ __forceinline__ void store2(float* C, size_t off, float x, float y) {
    *(float2*)&C[off] = make_float2(x, y);
}
__device__ __forceinline__ void store2(__half* C, size_t off, float x, float y) {
    *(__half2*)&C[off] = __floats2half2_rn(x, y);
}

// ---------------------------------------------------------------------------
// fp32 -> fp16 elementwise
// ---------------------------------------------------------------------------
__global__ void f2h_kernel(const float* __restrict__ in, __half* __restrict__ out, int n)
{
    int i = (blockIdx.x * blockDim.x + threadIdx.x) * 4;
    if (i < n) {
        float4 v = *(const float4*)&in[i];
        *(__half2*)&out[i]     = __floats2half2_rn(v.x, v.y);
        *(__half2*)&out[i + 2] = __floats2half2_rn(v.z, v.w);
    }
}

// ---------------------------------------------------------------------------
// Weight transpose + half convert: in fp32 [K][N] -> out half [N][K]
// ---------------------------------------------------------------------------
__global__ __launch_bounds__(256) void transpose_h(
    const float* __restrict__ in, __half* __restrict__ out, int K, int N)
{
    __shared__ float t[32][33];
    const int k0 = blockIdx.y * 32, n0 = blockIdx.x * 32;
    const int tx = threadIdx.x, ty = threadIdx.y;  // 32 x 8
#pragma unroll
    for (int r = ty; r < 32; r += 8)
        t[r][tx] = in[(size_t)(k0 + r) * N + n0 + tx];
    __syncthreads();
#pragma unroll
    for (int r = ty; r < 32; r += 8)
        out[(size_t)(n0 + r) * K + k0 + tx] = __float2half(t[tx][r]);
}

// ---------------------------------------------------------------------------
// fp16 GEMM with 3-stage cp.async pipeline.
// C[M,N] = A[M,K] @ Bt[N,K]^T.  128x128 tile, BK=32, 8 warps (2m x 4n).
// ---------------------------------------------------------------------------
#define GPAD 40
#define GBUF (128 * GPAD)                    // halves per operand stage
#define STAGES 3
#define HGEMM_SMEM (2 * STAGES * GBUF * 2)   // 61440 B

template <typename TO>
__global__ __launch_bounds__(256) void hgemm(
    const __half* __restrict__ A, const __half* __restrict__ Bt,
    TO* __restrict__ C, int M, int N, int K)
{
    __half* Asm = (__half*)dsmem;            // [STAGES][GBUF]
    __half* Bsm = Asm + STAGES * GBUF;       // [STAGES][GBUF]
    const uint32_t sA = smem_u32(Asm), sB = smem_u32(Bsm);

    const int tid = threadIdx.x, lane = tid & 31, warp = tid >> 5;
    const int wm = warp & 1, wn = warp >> 1;
    const int g = lane >> 2, t = lane & 3;
    const int srow = tid >> 1, sk = (tid & 1) * 16;

    const int ra = (lane & 7) + 8 * ((lane >> 3) & 1);
    const int ca = 8 * (lane >> 4);
    const int rb = (lane & 7) + 8 * (lane >> 4);
    const int cb = 8 * ((lane >> 3) & 1);

    const __half* Ag = A + (size_t)(blockIdx.y * 128 + srow) * K + sk;
    const __half* Bg = Bt + (size_t)(blockIdx.x * 128 + srow) * K + sk;
    const uint32_t stOff = (uint32_t)(srow * GPAD + sk) * 2;

    float acc[4][4][4];
#pragma unroll
    for (int i = 0; i < 4; i++)
#pragma unroll
        for (int j = 0; j < 4; j++)
#pragma unroll
            for (int c = 0; c < 4; c++) acc[i][j][c] = 0.f;

    const int KT = K / 32;

    // prologue: stages 0, 1
#pragma unroll
    for (int p = 0; p < 2; p++) {
        uint32_t da = sA + p * GBUF * 2 + stOff;
        uint32_t db = sB + p * GBUF * 2 + stOff;
        cpa16(da, Ag + p * 32);  cpa16(da + 16, Ag + p * 32 + 8);
        cpa16(db, Bg + p * 32);  cpa16(db + 16, Bg + p * 32 + 8);
        CP_COMMIT();
    }

    for (int it = 0; it < KT; it++) {
        CP_WAIT1();
        __syncthreads();
        if (it + 2 < KT) {
            const int st = (it + 2) % STAGES;
            uint32_t da = sA + st * GBUF * 2 + stOff;
            uint32_t db = sB + st * GBUF * 2 + stOff;
            cpa16(da, Ag + (it + 2) * 32);  cpa16(da + 16, Ag + (it + 2) * 32 + 8);
            cpa16(db, Bg + (it + 2) * 32);  cpa16(db + 16, Bg + (it + 2) * 32 + 8);
        }
        CP_COMMIT();

        const uint32_t bA = sA + (it % STAGES) * GBUF * 2;
        const uint32_t bB = sB + (it % STAGES) * GBUF * 2;
#pragma unroll
        for (int ks = 0; ks < 2; ks++) {
            const int k0 = ks * 16;
            uint32_t af[4][4];
#pragma unroll
            for (int mt = 0; mt < 4; mt++)
                ldm_x4(af[mt], bA + ((wm * 64 + mt * 16 + ra) * GPAD + k0 + ca) * 2);
#pragma unroll
            for (int bp = 0; bp < 2; bp++) {
                uint32_t b4[4];
                ldm_x4(b4, bB + ((wn * 32 + bp * 16 + rb) * GPAD + k0 + cb) * 2);
#pragma unroll
                for (int mt = 0; mt < 4; mt++) {
                    mma_f16(acc[mt][2 * bp],     af[mt], b4[0], b4[1]);
                    mma_f16(acc[mt][2 * bp + 1], af[mt], b4[2], b4[3]);
                }
            }
        }
    }

#pragma unroll
    for (int mt = 0; mt < 4; mt++) {
        const int row = blockIdx.y * 128 + wm * 64 + mt * 16 + g;
#pragma unroll
        for (int nt = 0; nt < 4; nt++) {
            const int col = blockIdx.x * 128 + wn * 32 + nt * 8 + 2 * t;
            store2(C, (size_t)row * N + col,       acc[mt][nt][0], acc[mt][nt][1]);
            store2(C, (size_t)(row + 8) * N + col, acc[mt][nt][2], acc[mt][nt][3]);
        }
    }
}

// ---------------------------------------------------------------------------
// RoPE (x4 vectorized): read fp32 [rows][64], write half, optional pre-scale
// ---------------------------------------------------------------------------
__global__ void rope_h4(const float* __restrict__ p, __half* __restrict__ ph,
                        int nheads, int total4,
                        const float* __restrict__ cs, const float* __restrict__ sn,
                        float scale)
{
    int idx = blockIdx.x * blockDim.x + threadIdx.x;
    if (idx >= total4) return;
    const int d4 = (idx & 7) * 4;
    const int rest = idx >> 3;
    const int s = (rest / nheads) % SEQ;
    const size_t base = (size_t)rest * HD;
    float4 lo = *(const float4*)&p[base + d4];
    float4 hi = *(const float4*)&p[base + d4 + 32];
    float4 c0 = *(const float4*)&cs[s * HD + d4];
    float4 s0 = *(const float4*)&sn[s * HD + d4];
    float4 c1 = *(const float4*)&cs[s * HD + d4 + 32];
    float4 s1 = *(const float4*)&sn[s * HD + d4 + 32];
    *(__half2*)&ph[base + d4] = __floats2half2_rn(
        (lo.x * c0.x - hi.x * s0.x) * scale, (lo.y * c0.y - hi.y * s0.y) * scale);
    *(__half2*)&ph[base + d4 + 2] = __floats2half2_rn(
        (lo.z * c0.z - hi.z * s0.z) * scale, (lo.w * c0.w - hi.w * s0.w) * scale);
    *(__half2*)&ph[base + d4 + 32] = __floats2half2_rn(
        (hi.x * c1.x + lo.x * s1.x) * scale, (hi.y * c1.y + lo.y * s1.y) * scale);
    *(__half2*)&ph[base + d4 + 34] = __floats2half2_rn(
        (hi.z * c1.z + lo.z * s1.z) * scale, (hi.w * c1.w + lo.w * s1.w) * scale);
}

// ---------------------------------------------------------------------------
// fp16 flash attention with 3-stage cp.async K/V ring.
// Block = (128 q rows, h, b). 8 warps x 16 rows. KV chunks of 64.
// ---------------------------------------------------------------------------
#define APAD 72
#define KVBUF (64 * APAD)
#define ATTN_SMEM ((128 + 3 * 64 + 3 * 64 + 128) * APAD * 2)   // 92160 B

__global__ __launch_bounds__(256) void attn_h(
    const __half* __restrict__ Qg, const __half* __restrict__ Kg,
    const __half* __restrict__ Vg, __half* __restrict__ Og)
{
    __half* Qs = (__half*)dsmem;             // [128][APAD]
    __half* Ks = Qs + 128 * APAD;            // [3][64][APAD]
    __half* Vs = Ks + 3 * KVBUF;             // [3][64][APAD]
    __half* Ps = Vs + 3 * KVBUF;             // [128][APAD]
    const uint32_t sQ = smem_u32(Qs), sK = smem_u32(Ks),
                   sV = smem_u32(Vs), sP = smem_u32(Ps);

    const int qb = blockIdx.x, h = blockIdx.y, b = blockIdx.z;
    const int kvh = h >> 2;
    const int tid = threadIdx.x;
    const int warp = tid >> 5, lane = tid & 31;
    const int g = lane >> 2, t = lane & 3;
    const int rowbase = warp * 16;

    const int ra = (lane & 7) + 8 * ((lane >> 3) & 1);
    const int ca = 8 * (lane >> 4);
    const int rb = (lane & 7) + 8 * (lane >> 4);
    const int cb = 8 * ((lane >> 3) & 1);

    const int nchunks = 2 * (qb + 1);
    const int svrow = tid >> 2;
    const int svc   = (tid & 3) * 16;
    const uint32_t kvOff = (uint32_t)(svrow * APAD + svc) * 2;
    const size_t gstride = (size_t)64 * NKV * HD;
    const __half* Kgp = Kg + (((size_t)b * SEQ + svrow) * NKV + kvh) * HD + svc;
    const __half* Vgp = Vg + (((size_t)b * SEQ + svrow) * NKV + kvh) * HD + svc;

    // prologue: issue KV chunks 0, 1
#pragma unroll
    for (int p = 0; p < 2; p++) {
        uint32_t dk = sK + p * KVBUF * 2 + kvOff;
        uint32_t dv = sV + p * KVBUF * 2 + kvOff;
        cpa16(dk, Kgp + p * gstride);  cpa16(dk + 16, Kgp + p * gstride + 8);
        cpa16(dv, Vgp + p * gstride);  cpa16(dv + 16, Vgp + p * gstride + 8);
        CP_COMMIT();
    }

    // ---- stage Q tile (regular stores; overlaps with cp.async above) ----
    {
        const int row = tid & 127;
        const int c0 = (tid >> 7) * 32;
        const __half* src = &Qg[(((size_t)b * SEQ + qb * 128 + row) * NH + h) * HD + c0];
        uint32_t d = sQ + (row * APAD + c0) * 2;
#pragma unroll
        for (int i = 0; i < 4; i++) {
            uint4 v = *(const uint4*)(src + 8 * i);
            asm volatile("st.shared.v4.b32 [%0], {%1,%2,%3,%4};" :: "r"(d + 16 * i),
                         "r"(v.x), "r"(v.y), "r"(v.z), "r"(v.w) : "memory");
        }
    }
    __syncthreads();

    uint32_t qf[4][4];
#pragma unroll
    for (int kt = 0; kt < 4; kt++)
        ldm_x4(qf[kt], sQ + ((rowbase + ra) * APAD + kt * 16 + ca) * 2);

    float m0r = -1e30f, m1r = -1e30f, l0r = 0.f, l1r = 0.f;
    float of[8][4];
#pragma unroll
    for (int nt = 0; nt < 8; nt++)
#pragma unroll
        for (int c = 0; c < 4; c++) of[nt][c] = 0.f;

    for (int kc = 0; kc < nchunks; kc++) {
        CP_WAIT1();
        __syncthreads();
        if (kc + 2 < nchunks) {
            const int st = (kc + 2) % 3;
            uint32_t dk = sK + st * KVBUF * 2 + kvOff;
            uint32_t dv = sV + st * KVBUF * 2 + kvOff;
            cpa16(dk, Kgp + (size_t)(kc + 2) * gstride);
            cpa16(dk + 16, Kgp + (size_t)(kc + 2) * gstride + 8);
            cpa16(dv, Vgp + (size_t)(kc + 2) * gstride);
            cpa16(dv + 16, Vgp + (size_t)(kc + 2) * gstride + 8);
        }
        CP_COMMIT();

        const uint32_t bK = sK + (kc % 3) * KVBUF * 2;
        const uint32_t bV = sV + (kc % 3) * KVBUF * 2;

        // ---- S = Q K^T ----
        float sf[8][4];
#pragma unroll
        for (int nt = 0; nt < 8; nt++)
#pragma unroll
            for (int c = 0; c < 4; c++) sf[nt][c] = 0.f;

#pragma unroll
        for (int kt = 0; kt < 4; kt++) {
#pragma unroll
            for (int bp = 0; bp < 4; bp++) {
                uint32_t b4[4];
                ldm_x4(b4, bK + ((bp * 16 + rb) * APAD + kt * 16 + cb) * 2);
                mma_f16(sf[2 * bp],     qf[kt], b4[0], b4[1]);
                mma_f16(sf[2 * bp + 1], qf[kt], b4[2], b4[3]);
            }
        }

        // ---- causal mask ----
        const int qr0 = qb * 128 + rowbase + g;
        const int qr1 = qr0 + 8;
        if (kc * 64 + 63 > qr0) {
#pragma unroll
            for (int nt = 0; nt < 8; nt++) {
                const int kv0 = kc * 64 + nt * 8 + 2 * t;
                if (kv0 > qr0)     sf[nt][0] = -1e30f;
                if (kv0 + 1 > qr0) sf[nt][1] = -1e30f;
                if (kv0 > qr1)     sf[nt][2] = -1e30f;
                if (kv0 + 1 > qr1) sf[nt][3] = -1e30f;
            }
        }

        // ---- online softmax (fp32) ----
        float mx0 = -1e30f, mx1 = -1e30f;
#pragma unroll
        for (int nt = 0; nt < 8; nt++) {
            mx0 = fmaxf(mx0, fmaxf(sf[nt][0], sf[nt][1]));
            mx1 = fmaxf(mx1, fmaxf(sf[nt][2], sf[nt][3]));
        }
        mx0 = fmaxf(mx0, __shfl_xor_sync(0xffffffffu, mx0, 1));
        mx0 = fmaxf(mx0, __shfl_xor_sync(0xffffffffu, mx0, 2));
        mx1 = fmaxf(mx1, __shfl_xor_sync(0xffffffffu, mx1, 1));
        mx1 = fmaxf(mx1, __shfl_xor_sync(0xffffffffu, mx1, 2));

        const float mn0 = fmaxf(m0r, mx0);
        const float mn1 = fmaxf(m1r, mx1);
        const float al0 = __expf(m0r - mn0);
        const float al1 = __expf(m1r - mn1);
        m0r = mn0; m1r = mn1;

        float ps0 = 0.f, ps1 = 0.f;
#pragma unroll
        for (int nt = 0; nt < 8; nt++) {
            sf[nt][0] = __expf(sf[nt][0] - mn0);
            sf[nt][1] = __expf(sf[nt][1] - mn0);
            sf[nt][2] = __expf(sf[nt][2] - mn1);
            sf[nt][3] = __expf(sf[nt][3] - mn1);
            ps0 += sf[nt][0] + sf[nt][1];
            ps1 += sf[nt][2] + sf[nt][3];
        }
        ps0 += __shfl_xor_sync(0xffffffffu, ps0, 1);
        ps0 += __shfl_xor_sync(0xffffffffu, ps0, 2);
        ps1 += __shfl_xor_sync(0xffffffffu, ps1, 1);
        ps1 += __shfl_xor_sync(0xffffffffu, ps1, 2);
        l0r = l0r * al0 + ps0;
        l1r = l1r * al1 + ps1;

#pragma unroll
        for (int nt = 0; nt < 8; nt++) {
            of[nt][0] *= al0; of[nt][1] *= al0;
            of[nt][2] *= al1; of[nt][3] *= al1;
        }

        // ---- stage P as half (warp-private rows) ----
#pragma unroll
        for (int nt = 0; nt < 8; nt++) {
            *(__half2*)&Ps[(rowbase + g) * APAD + nt * 8 + 2 * t] =
                __floats2half2_rn(sf[nt][0], sf[nt][1]);
            *(__half2*)&Ps[(rowbase + g + 8) * APAD + nt * 8 + 2 * t] =
                __floats2half2_rn(sf[nt][2], sf[nt][3]);
        }
        __syncwarp();

        // ---- O += P @ V ----
#pragma unroll
        for (int kt = 0; kt < 4; kt++) {
            uint32_t pf[4];
            ldm_x4(pf, sP + ((rowbase + ra) * APAD + kt * 16 + ca) * 2);
#pragma unroll
            for (int bp = 0; bp < 4; bp++) {
                uint32_t b4[4];
                ldm_x4t(b4, bV + ((kt * 16 + ra) * APAD + bp * 16 + ca) * 2);
                mma_f16(of[2 * bp],     pf, b4[0], b4[1]);
                mma_f16(of[2 * bp + 1], pf, b4[2], b4[3]);
            }
        }
    }

    // ---- epilogue (half out) ----
    const float inv0 = 1.f / l0r, inv1 = 1.f / l1r;
    const int row0 = qb * 128 + rowbase + g;
#pragma unroll
    for (int nt = 0; nt < 8; nt++) {
        const int col = nt * 8 + 2 * t;
        *(__half2*)&Og[(((size_t)b * SEQ + row0) * NH + h) * HD + col] =
            __floats2half2_rn(of[nt][0] * inv0, of[nt][1] * inv0);
        *(__half2*)&Og[(((size_t)b * SEQ + row0 + 8) * NH + h) * HD + col] =
            __floats2half2_rn(of[nt][2] * inv1, of[nt][3] * inv1);
    }
}

// ---------------------------------------------------------------------------
extern "C" void kernel_launch(void* const* d_in, const int* in_sizes, int n_in,
                              void* d_out, int out_size)
{
    const float* x  = (const float*)d_in[0];
    const float* Wq = (const float*)d_in[1];
    const float* Wk = (const float*)d_in[2];
    const float* Wv = (const float*)d_in[3];
    const float* Wo = (const float*)d_in[4];
    const float* cs = (const float*)d_in[5];
    const float* sn = (const float*)d_in[6];
    float* out = (float*)d_out;

    float *qf, *kf;
    __half *xh, *qh, *kh, *vh, *oh, *wqt, *wkt, *wvt, *wot;
    cudaGetSymbolAddress((void**)&qf, g_qf);
    cudaGetSymbolAddress((void**)&kf, g_kf);
    cudaGetSymbolAddress((void**)&xh, g_xh);
    cudaGetSymbolAddress((void**)&qh, g_qh);
    cudaGetSymbolAddress((void**)&kh, g_kh);
    cudaGetSymbolAddress((void**)&vh, g_vh);
    cudaGetSymbolAddress((void**)&oh, g_oh);
    cudaGetSymbolAddress((void**)&wqt, g_wqt);
    cudaGetSymbolAddress((void**)&wkt, g_wkt);
    cudaGetSymbolAddress((void**)&wvt, g_wvt);
    cudaGetSymbolAddress((void**)&wot, g_wot);

    cudaFuncSetAttribute(attn_h, cudaFuncAttributeMaxDynamicSharedMemorySize, ATTN_SMEM);
    cudaFuncSetAttribute(hgemm<float>, cudaFuncAttributeMaxDynamicSharedMemorySize, HGEMM_SMEM);
    cudaFuncSetAttribute(hgemm<__half>, cudaFuncAttributeMaxDynamicSharedMemorySize, HGEMM_SMEM);

    const int M = MTOT;  // 4096

    // x -> half
    f2h_kernel<<<(M * DIM / 4 + 255) / 256, 256>>>(x, xh, M * DIM);

    // weight transposes (fp32 [K][N] -> half [N][K])
    transpose_h<<<dim3(DIM / 32, DIM / 32), dim3(32, 8)>>>(Wq, wqt, DIM, DIM);
    transpose_h<<<dim3((NKV * HD) / 32, DIM / 32), dim3(32, 8)>>>(Wk, wkt, DIM, NKV * HD);
    transpose_h<<<dim3((NKV * HD) / 32, DIM / 32), dim3(32, 8)>>>(Wv, wvt, DIM, NKV * HD);
    transpose_h<<<dim3(DIM / 32, DIM / 32), dim3(32, 8)>>>(Wo, wot, DIM, DIM);

    // projections
    hgemm<float><<<dim3(DIM / 128, M / 128), 256, HGEMM_SMEM>>>(xh, wqt, qf, M, DIM, DIM);
    hgemm<float><<<dim3((NKV * HD) / 128, M / 128), 256, HGEMM_SMEM>>>(xh, wkt, kf, M, NKV * HD, DIM);
    hgemm<__half><<<dim3((NKV * HD) / 128, M / 128), 256, HGEMM_SMEM>>>(xh, wvt, vh, M, NKV * HD, DIM);

    // rope -> half (q pre-scaled)
    const int qtot4 = MTOT * NH * 8;
    const int ktot4 = MTOT * NKV * 8;
    rope_h4<<<(qtot4 + 255) / 256, 256>>>(qf, qh, NH, qtot4, cs, sn, ATT_SCALE);
    rope_h4<<<(ktot4 + 255) / 256, 256>>>(kf, kh, NKV, ktot4, cs, sn, 1.0f);

    // attention
    attn_h<<<dim3(SEQ / 128, NH, BATCH), 256, ATTN_SMEM>>>(qh, kh, vh, oh);

    // output projection
    hgemm<float><<<dim3(DIM / 128, M / 128), 256, HGEMM_SMEM>>>(oh, wot, out, M, DIM, DIM);
}

// round 7
// speedup vs baseline: 7.1287x; 1.0947x over previous
#include <cuda_runtime.h>
#include <cuda_fp16.h>
#include <cstdint>

#define BATCH 2
#define SEQ 2048
#define DIM 2048
#define NH 32
#define NKV 8
#define HD 64
#define MTOT (BATCH * SEQ)
// Q pre-scale: 1/sqrt(64) * log2(e)  (softmax runs in log2 domain)
#define QSCALE 0.18033688011112042f

extern __shared__ char dsmem[];

// Scratch (no cudaMalloc allowed)
__device__ __half g_xh[MTOT * DIM];
__device__ __half g_qp[MTOT * NH * HD];       // pre-rope q (half)
__device__ __half g_kp[MTOT * NKV * HD];      // pre-rope k (half)
__device__ __half g_qh[MTOT * NH * HD];
__device__ __half g_kh[MTOT * NKV * HD];
__device__ __half g_vh[MTOT * NKV * HD];
__device__ __half g_oh[MTOT * NH * HD];
__device__ __half g_wqkvt[3072 * DIM];        // [Wq^T; Wk^T; Wv^T] rows
__device__ __half g_wot[DIM * DIM];

// ---------------------------------------------------------------------------
// helpers
// ---------------------------------------------------------------------------
__device__ __forceinline__ uint32_t smem_u32(const void* p) {
    uint32_t a;
    asm("{ .reg .u64 t; cvta.to.shared.u64 t, %1; cvt.u32.u64 %0, t; }" : "=r"(a) : "l"(p));
    return a;
}

__device__ __forceinline__ void cpa16(uint32_t dst, const void* src) {
    asm volatile("cp.async.cg.shared.global [%0], [%1], 16;" :: "r"(dst), "l"(src) : "memory");
}
#define CP_COMMIT() asm volatile("cp.async.commit_group;" ::: "memory")
#define CP_WAIT1()  asm volatile("cp.async.wait_group 1;" ::: "memory")

__device__ __forceinline__ void ldm_x4(uint32_t r[4], uint32_t addr) {
    asm volatile("ldmatrix.sync.aligned.m8n8.x4.shared.b16 {%0,%1,%2,%3}, [%4];"
                 : "=r"(r[0]), "=r"(r[1]), "=r"(r[2]), "=r"(r[3]) : "r"(addr));
}
__device__ __forceinline__ void ldm_x4t(uint32_t r[4], uint32_t addr) {
    asm volatile("ldmatrix.sync.aligned.m8n8.x4.trans.shared.b16 {%0,%1,%2,%3}, [%4];"
                 : "=r"(r[0]), "=r"(r[1]), "=r"(r[2]), "=r"(r[3]) : "r"(addr));
}

__device__ __forceinline__ void mma_f16(float c[4], const uint32_t a[4],
                                        uint32_t b0, uint32_t b1) {
    asm volatile(
        "mma.sync.aligned.m16n8k16.row.col.f32.f16.f16.f32 "
        "{%0,%1,%2,%3}, {%4,%5,%6,%7}, {%8,%9}, {%0,%1,%2,%3};"
        : "+f"(c[0]), "+f"(c[1]), "+f"(c[2]), "+f"(c[3])
        : "r"(a[0]), "r"(a[1]), "r"(a[2]), "r"(a[3]), "r"(b0), "r"(b1));
}

__device__ __forceinline__ uint32_t packh2(float x, float y) {
    __half2 h = __floats2half2_rn(x, y);
    return *(uint32_t*)&h;
}

__device__ __forceinline__ void store2(float* C, size_t off, float x, float y) {
    *(float2*)&C[off] = make_float2(x, y);
}
__device__ __forceinline__ void store2(__half* C, size_t off, float x, float y) {
    *(__half2*)&C[off] = __floats2half2_rn(x, y);
}

// ---------------------------------------------------------------------------
// fp32 -> fp16 elementwise
// ---------------------------------------------------------------------------
__global__ void f2h_kernel(const float* __restrict__ in, __half* __restrict__ out, int n)
{
    int i = (blockIdx.x * blockDim.x + threadIdx.x) * 4;
    if (i < n) {
        float4 v = *(const float4*)&in[i];
        *(__half2*)&out[i]     = __floats2half2_rn(v.x, v.y);
        *(__half2*)&out[i + 2] = __floats2half2_rn(v.z, v.w);
    }
}

// ---------------------------------------------------------------------------
// Combined QKV weight transpose: Wq[2048][2048], Wk/Wv[2048][512] ->
// g_wqkvt rows: [0,2048)=Wq^T, [2048,2560)=Wk^T, [2560,3072)=Wv^T
// ---------------------------------------------------------------------------
__global__ __launch_bounds__(256) void transpose_qkv(
    const float* __restrict__ Wq, const float* __restrict__ Wk,
    const float* __restrict__ Wv, __half* __restrict__ out)
{
    __shared__ float tbuf[32][33];
    const int n0 = blockIdx.x * 32;   // combined col 0..3071
    const int k0 = blockIdx.y * 32;
    const float* src; int srcN, nloc;
    if (n0 < 2048)      { src = Wq; srcN = 2048; nloc = n0; }
    else if (n0 < 2560) { src = Wk; srcN = 512;  nloc = n0 - 2048; }
    else                { src = Wv; srcN = 512;  nloc = n0 - 2560; }
    const int tx = threadIdx.x, ty = threadIdx.y;  // 32 x 8
#pragma unroll
    for (int r = ty; r < 32; r += 8)
        tbuf[r][tx] = src[(size_t)(k0 + r) * srcN + nloc + tx];
    __syncthreads();
#pragma unroll
    for (int r = ty; r < 32; r += 8)
        out[(size_t)(n0 + r) * DIM + k0 + tx] = __float2half(tbuf[tx][r]);
}

__global__ __launch_bounds__(256) void transpose_h(
    const float* __restrict__ in, __half* __restrict__ out, int K, int N)
{
    __shared__ float tbuf[32][33];
    const int k0 = blockIdx.y * 32, n0 = blockIdx.x * 32;
    const int tx = threadIdx.x, ty = threadIdx.y;
#pragma unroll
    for (int r = ty; r < 32; r += 8)
        tbuf[r][tx] = in[(size_t)(k0 + r) * N + n0 + tx];
    __syncthreads();
#pragma unroll
    for (int r = ty; r < 32; r += 8)
        out[(size_t)(n0 + r) * K + k0 + tx] = __float2half(tbuf[tx][r]);
}

// ---------------------------------------------------------------------------
// GEMM core (3-stage cp.async, 128x128 tile, BK=32, 8 warps 2m x 4n)
// ---------------------------------------------------------------------------
#define GPAD 40
#define GBUF (128 * GPAD)
#define STAGES 3
#define HGEMM_SMEM (2 * STAGES * GBUF * 2)   // 61440 B

struct GemmAcc { float a[4][4][4]; };

template <typename EPI>
__device__ __forceinline__ void hgemm_core(
    const __half* Ag0, const __half* Bg0, int K, EPI epi)
{
    __half* Asm = (__half*)dsmem;
    __half* Bsm = Asm + STAGES * GBUF;
    const uint32_t sA = smem_u32(Asm), sB = smem_u32(Bsm);

    const int tid = threadIdx.x, lane = tid & 31, warp = tid >> 5;
    const int wm = warp & 1, wn = warp >> 1;
    const int g = lane >> 2, t = lane & 3;
    const int srow = tid >> 1, sk = (tid & 1) * 16;

    const int ra = (lane & 7) + 8 * ((lane >> 3) & 1);
    const int ca = 8 * (lane >> 4);
    const int rb = (lane & 7) + 8 * (lane >> 4);
    const int cb = 8 * ((lane >> 3) & 1);

    const __half* Ag = Ag0 + (size_t)srow * K + sk;
    const __half* Bg = Bg0 + (size_t)srow * K + sk;
    const uint32_t stOff = (uint32_t)(srow * GPAD + sk) * 2;

    GemmAcc acc;
#pragma unroll
    for (int i = 0; i < 4; i++)
#pragma unroll
        for (int j = 0; j < 4; j++)
#pragma unroll
            for (int c = 0; c < 4; c++) acc.a[i][j][c] = 0.f;

    const int KT = K / 32;
#pragma unroll
    for (int p = 0; p < 2; p++) {
        uint32_t da = sA + p * GBUF * 2 + stOff;
        uint32_t db = sB + p * GBUF * 2 + stOff;
        cpa16(da, Ag + p * 32);  cpa16(da + 16, Ag + p * 32 + 8);
        cpa16(db, Bg + p * 32);  cpa16(db + 16, Bg + p * 32 + 8);
        CP_COMMIT();
    }

    for (int it = 0; it < KT; it++) {
        CP_WAIT1();
        __syncthreads();
        if (it + 2 < KT) {
            const int st = (it + 2) % STAGES;
            uint32_t da = sA + st * GBUF * 2 + stOff;
            uint32_t db = sB + st * GBUF * 2 + stOff;
            cpa16(da, Ag + (it + 2) * 32);  cpa16(da + 16, Ag + (it + 2) * 32 + 8);
            cpa16(db, Bg + (it + 2) * 32);  cpa16(db + 16, Bg + (it + 2) * 32 + 8);
        }
        CP_COMMIT();

        const uint32_t bA = sA + (it % STAGES) * GBUF * 2;
        const uint32_t bB = sB + (it % STAGES) * GBUF * 2;
#pragma unroll
        for (int ks = 0; ks < 2; ks++) {
            const int k0 = ks * 16;
            uint32_t af[4][4];
#pragma unroll
            for (int mt = 0; mt < 4; mt++)
                ldm_x4(af[mt], bA + ((wm * 64 + mt * 16 + ra) * GPAD + k0 + ca) * 2);
#pragma unroll
            for (int bp = 0; bp < 2; bp++) {
                uint32_t b4[4];
                ldm_x4(b4, bB + ((wn * 32 + bp * 16 + rb) * GPAD + k0 + cb) * 2);
#pragma unroll
                for (int mt = 0; mt < 4; mt++) {
                    mma_f16(acc.a[mt][2 * bp],     af[mt], b4[0], b4[1]);
                    mma_f16(acc.a[mt][2 * bp + 1], af[mt], b4[2], b4[3]);
                }
            }
        }
    }
    epi(acc, wm, wn, g, t);
}

// QKV fused projection: A=xh, Bt=wqkvt[3072][2048]; writes qp/kp/vh (half)
__global__ __launch_bounds__(256) void hgemm_qkv(
    const __half* __restrict__ A, const __half* __restrict__ Bt,
    __half* __restrict__ Q, __half* __restrict__ Kc, __half* __restrict__ V)
{
    const int bx = blockIdx.x, by = blockIdx.y;
    __half* Cp; int colbase, stride;
    if (bx < 16)      { Cp = Q;  colbase = bx * 128;        stride = 2048; }
    else if (bx < 20) { Cp = Kc; colbase = (bx - 16) * 128; stride = 512;  }
    else              { Cp = V;  colbase = (bx - 20) * 128; stride = 512;  }
    hgemm_core(A + (size_t)(by * 128) * DIM, Bt + (size_t)(bx * 128) * DIM, DIM,
        [&](const GemmAcc& acc, int wm, int wn, int g, int t) {
#pragma unroll
            for (int mt = 0; mt < 4; mt++) {
                const int row = by * 128 + wm * 64 + mt * 16 + g;
#pragma unroll
                for (int nt = 0; nt < 4; nt++) {
                    const int col = colbase + wn * 32 + nt * 8 + 2 * t;
                    store2(Cp, (size_t)row * stride + col,
                           acc.a[mt][nt][0], acc.a[mt][nt][1]);
                    store2(Cp, (size_t)(row + 8) * stride + col,
                           acc.a[mt][nt][2], acc.a[mt][nt][3]);
                }
            }
        });
}

// generic: C fp32 [M][N]
__global__ __launch_bounds__(256) void hgemm_f(
    const __half* __restrict__ A, const __half* __restrict__ Bt,
    float* __restrict__ C, int N, int K)
{
    const int bx = blockIdx.x, by = blockIdx.y;
    hgemm_core(A + (size_t)(by * 128) * K, Bt + (size_t)(bx * 128) * K, K,
        [&](const GemmAcc& acc, int wm, int wn, int g, int t) {
#pragma unroll
            for (int mt = 0; mt < 4; mt++) {
                const int row = by * 128 + wm * 64 + mt * 16 + g;
#pragma unroll
                for (int nt = 0; nt < 4; nt++) {
                    const int col = bx * 128 + wn * 32 + nt * 8 + 2 * t;
                    store2(C, (size_t)row * N + col, acc.a[mt][nt][0], acc.a[mt][nt][1]);
                    store2(C, (size_t)(row + 8) * N + col, acc.a[mt][nt][2], acc.a[mt][nt][3]);
                }
            }
        });
}

// ---------------------------------------------------------------------------
// RoPE: half in -> half out, 4 (lo,hi) pairs per thread, optional pre-scale
// ---------------------------------------------------------------------------
__global__ void rope_hh(const __half* __restrict__ in, __half* __restrict__ out,
                        int nheads, int total4,
                        const float* __restrict__ cs, const float* __restrict__ sn,
                        float scale)
{
    int idx = blockIdx.x * blockDim.x + threadIdx.x;
    if (idx >= total4) return;
    const int d4 = (idx & 7) * 4;
    const int rest = idx >> 3;
    const int s = (rest / nheads) % SEQ;
    const size_t base = (size_t)rest * HD;
    uint2 lo2 = *(const uint2*)&in[base + d4];
    uint2 hi2 = *(const uint2*)&in[base + d4 + 32];
    const __half2* lh = (const __half2*)&lo2;
    const __half2* hh = (const __half2*)&hi2;
    float2 l01 = __half22float2(lh[0]), l23 = __half22float2(lh[1]);
    float2 h01 = __half22float2(hh[0]), h23 = __half22float2(hh[1]);
    float4 c0 = *(const float4*)&cs[s * HD + d4];
    float4 s0 = *(const float4*)&sn[s * HD + d4];
    float4 c1 = *(const float4*)&cs[s * HD + d4 + 32];
    float4 s1 = *(const float4*)&sn[s * HD + d4 + 32];
    *(__half2*)&out[base + d4] = __floats2half2_rn(
        (l01.x * c0.x - h01.x * s0.x) * scale, (l01.y * c0.y - h01.y * s0.y) * scale);
    *(__half2*)&out[base + d4 + 2] = __floats2half2_rn(
        (l23.x * c0.z - h23.x * s0.z) * scale, (l23.y * c0.w - h23.y * s0.w) * scale);
    *(__half2*)&out[base + d4 + 32] = __floats2half2_rn(
        (h01.x * c1.x + l01.x * s1.x) * scale, (h01.y * c1.y + l01.y * s1.y) * scale);
    *(__half2*)&out[base + d4 + 34] = __floats2half2_rn(
        (h23.x * c1.z + l23.x * s1.z) * scale, (h23.y * c1.w + l23.y * s1.w) * scale);
}

// ---------------------------------------------------------------------------
// fp16 flash attention: cp.async KV ring + register P conversion + exp2.
// ---------------------------------------------------------------------------
#define APAD 72
#define KVBUF (64 * APAD)
#define ATTN_SMEM ((128 + 3 * 64 + 3 * 64) * APAD * 2)   // 73728 B

__global__ __launch_bounds__(256) void attn_h(
    const __half* __restrict__ Qg, const __half* __restrict__ Kg,
    const __half* __restrict__ Vg, __half* __restrict__ Og)
{
    __half* Qs = (__half*)dsmem;             // [128][APAD]
    __half* Ks = Qs + 128 * APAD;            // [3][64][APAD]
    __half* Vs = Ks + 3 * KVBUF;             // [3][64][APAD]
    const uint32_t sQ = smem_u32(Qs), sK = smem_u32(Ks), sV = smem_u32(Vs);

    const int qb = blockIdx.x, h = blockIdx.y, b = blockIdx.z;
    const int kvh = h >> 2;
    const int tid = threadIdx.x;
    const int warp = tid >> 5, lane = tid & 31;
    const int g = lane >> 2, t = lane & 3;
    const int rowbase = warp * 16;

    const int ra = (lane & 7) + 8 * ((lane >> 3) & 1);
    const int ca = 8 * (lane >> 4);
    const int rb = (lane & 7) + 8 * (lane >> 4);
    const int cb = 8 * ((lane >> 3) & 1);

    const int nchunks = 2 * (qb + 1);
    const int svrow = tid >> 2;
    const int svc   = (tid & 3) * 16;
    const uint32_t kvOff = (uint32_t)(svrow * APAD + svc) * 2;
    const size_t gstride = (size_t)64 * NKV * HD;
    const __half* Kgp = Kg + (((size_t)b * SEQ + svrow) * NKV + kvh) * HD + svc;
    const __half* Vgp = Vg + (((size_t)b * SEQ + svrow) * NKV + kvh) * HD + svc;

#pragma unroll
    for (int p = 0; p < 2; p++) {
        uint32_t dk = sK + p * KVBUF * 2 + kvOff;
        uint32_t dv = sV + p * KVBUF * 2 + kvOff;
        cpa16(dk, Kgp + p * gstride);  cpa16(dk + 16, Kgp + p * gstride + 8);
        cpa16(dv, Vgp + p * gstride);  cpa16(dv + 16, Vgp + p * gstride + 8);
        CP_COMMIT();
    }

    {
        const int row = tid & 127;
        const int c0 = (tid >> 7) * 32;
        const __half* src = &Qg[(((size_t)b * SEQ + qb * 128 + row) * NH + h) * HD + c0];
        uint32_t d = sQ + (row * APAD + c0) * 2;
#pragma unroll
        for (int i = 0; i < 4; i++) {
            uint4 v = *(const uint4*)(src + 8 * i);
            asm volatile("st.shared.v4.b32 [%0], {%1,%2,%3,%4};" :: "r"(d + 16 * i),
                         "r"(v.x), "r"(v.y), "r"(v.z), "r"(v.w) : "memory");
        }
    }
    __syncthreads();

    uint32_t qf[4][4];
#pragma unroll
    for (int kt = 0; kt < 4; kt++)
        ldm_x4(qf[kt], sQ + ((rowbase + ra) * APAD + kt * 16 + ca) * 2);

    float m0r = -1e30f, m1r = -1e30f, l0r = 0.f, l1r = 0.f;
    float of[8][4];
#pragma unroll
    for (int nt = 0; nt < 8; nt++)
#pragma unroll
        for (int c = 0; c < 4; c++) of[nt][c] = 0.f;

    for (int kc = 0; kc < nchunks; kc++) {
        CP_WAIT1();
        __syncthreads();
        if (kc + 2 < nchunks) {
            const int st = (kc + 2) % 3;
            uint32_t dk = sK + st * KVBUF * 2 + kvOff;
            uint32_t dv = sV + st * KVBUF * 2 + kvOff;
            cpa16(dk, Kgp + (size_t)(kc + 2) * gstride);
            cpa16(dk + 16, Kgp + (size_t)(kc + 2) * gstride + 8);
            cpa16(dv, Vgp + (size_t)(kc + 2) * gstride);
            cpa16(dv + 16, Vgp + (size_t)(kc + 2) * gstride + 8);
        }
        CP_COMMIT();

        const uint32_t bK = sK + (kc % 3) * KVBUF * 2;
        const uint32_t bV = sV + (kc % 3) * KVBUF * 2;

        // ---- S = Q K^T (log2-domain scores; Q pre-scaled) ----
        float sf[8][4];
#pragma unroll
        for (int nt = 0; nt < 8; nt++)
#pragma unroll
            for (int c = 0; c < 4; c++) sf[nt][c] = 0.f;

#pragma unroll
        for (int kt = 0; kt < 4; kt++) {
#pragma unroll
            for (int bp = 0; bp < 4; bp++) {
                uint32_t b4[4];
                ldm_x4(b4, bK + ((bp * 16 + rb) * APAD + kt * 16 + cb) * 2);
                mma_f16(sf[2 * bp],     qf[kt], b4[0], b4[1]);
                mma_f16(sf[2 * bp + 1], qf[kt], b4[2], b4[3]);
            }
        }

        // ---- causal mask ----
        const int qr0 = qb * 128 + rowbase + g;
        const int qr1 = qr0 + 8;
        if (kc * 64 + 63 > qr0) {
#pragma unroll
            for (int nt = 0; nt < 8; nt++) {
                const int kv0 = kc * 64 + nt * 8 + 2 * t;
                if (kv0 > qr0)     sf[nt][0] = -1e30f;
                if (kv0 + 1 > qr0) sf[nt][1] = -1e30f;
                if (kv0 > qr1)     sf[nt][2] = -1e30f;
                if (kv0 + 1 > qr1) sf[nt][3] = -1e30f;
            }
        }

        // ---- online softmax (exp2) ----
        float mx0 = -1e30f, mx1 = -1e30f;
#pragma unroll
        for (int nt = 0; nt < 8; nt++) {
            mx0 = fmaxf(mx0, fmaxf(sf[nt][0], sf[nt][1]));
            mx1 = fmaxf(mx1, fmaxf(sf[nt][2], sf[nt][3]));
        }
        mx0 = fmaxf(mx0, __shfl_xor_sync(0xffffffffu, mx0, 1));
        mx0 = fmaxf(mx0, __shfl_xor_sync(0xffffffffu, mx0, 2));
        mx1 = fmaxf(mx1, __shfl_xor_sync(0xffffffffu, mx1, 1));
        mx1 = fmaxf(mx1, __shfl_xor_sync(0xffffffffu, mx1, 2));

        const float mn0 = fmaxf(m0r, mx0);
        const float mn1 = fmaxf(m1r, mx1);
        const float al0 = exp2f(m0r - mn0);
        const float al1 = exp2f(m1r - mn1);
        m0r = mn0; m1r = mn1;

        float ps0 = 0.f, ps1 = 0.f;
#pragma unroll
        for (int nt = 0; nt < 8; nt++) {
            sf[nt][0] = exp2f(sf[nt][0] - mn0);
            sf[nt][1] = exp2f(sf[nt][1] - mn0);
            sf[nt][2] = exp2f(sf[nt][2] - mn1);
            sf[nt][3] = exp2f(sf[nt][3] - mn1);
            ps0 += sf[nt][0] + sf[nt][1];
            ps1 += sf[nt][2] + sf[nt][3];
        }
        ps0 += __shfl_xor_sync(0xffffffffu, ps0, 1);
        ps0 += __shfl_xor_sync(0xffffffffu, ps0, 2);
        ps1 += __shfl_xor_sync(0xffffffffu, ps1, 1);
        ps1 += __shfl_xor_sync(0xffffffffu, ps1, 2);
        l0r = l0r * al0 + ps0;
        l1r = l1r * al1 + ps1;

#pragma unroll
        for (int nt = 0; nt < 8; nt++) {
            of[nt][0] *= al0; of[nt][1] *= al0;
            of[nt][2] *= al1; of[nt][3] *= al1;
        }

        // ---- O += P @ V : P converted C-frag -> A-frag in registers ----
#pragma unroll
        for (int j = 0; j < 4; j++) {
            uint32_t pa[4];
            pa[0] = packh2(sf[2 * j][0],     sf[2 * j][1]);
            pa[1] = packh2(sf[2 * j][2],     sf[2 * j][3]);
            pa[2] = packh2(sf[2 * j + 1][0], sf[2 * j + 1][1]);
            pa[3] = packh2(sf[2 * j + 1][2], sf[2 * j + 1][3]);
#pragma unroll
            for (int bp = 0; bp < 4; bp++) {
                uint32_t b4[4];
                ldm_x4t(b4, bV + ((j * 16 + ra) * APAD + bp * 16 + ca) * 2);
                mma_f16(of[2 * bp],     pa, b4[0], b4[1]);
                mma_f16(of[2 * bp + 1], pa, b4[2], b4[3]);
            }
        }
    }

    // ---- epilogue (half out) ----
    const float inv0 = 1.f / l0r, inv1 = 1.f / l1r;
    const int row0 = qb * 128 + rowbase + g;
#pragma unroll
    for (int nt = 0; nt < 8; nt++) {
        const int col = nt * 8 + 2 * t;
        *(__half2*)&Og[(((size_t)b * SEQ + row0) * NH + h) * HD + col] =
            __floats2half2_rn(of[nt][0] * inv0, of[nt][1] * inv0);
        *(__half2*)&Og[(((size_t)b * SEQ + row0 + 8) * NH + h) * HD + col] =
            __floats2half2_rn(of[nt][2] * inv1, of[nt][3] * inv1);
    }
}

// ---------------------------------------------------------------------------
extern "C" void kernel_launch(void* const* d_in, const int* in_sizes, int n_in,
                              void* d_out, int out_size)
{
    const float* x  = (const float*)d_in[0];
    const float* Wq = (const float*)d_in[1];
    const float* Wk = (const float*)d_in[2];
    const float* Wv = (const float*)d_in[3];
    const float* Wo = (const float*)d_in[4];
    const float* cs = (const float*)d_in[5];
    const float* sn = (const float*)d_in[6];
    float* out = (float*)d_out;

    __half *xh, *qp, *kp, *qh, *kh, *vh, *oh, *wqkvt, *wot;
    cudaGetSymbolAddress((void**)&xh, g_xh);
    cudaGetSymbolAddress((void**)&qp, g_qp);
    cudaGetSymbolAddress((void**)&kp, g_kp);
    cudaGetSymbolAddress((void**)&qh, g_qh);
    cudaGetSymbolAddress((void**)&kh, g_kh);
    cudaGetSymbolAddress((void**)&vh, g_vh);
    cudaGetSymbolAddress((void**)&oh, g_oh);
    cudaGetSymbolAddress((void**)&wqkvt, g_wqkvt);
    cudaGetSymbolAddress((void**)&wot, g_wot);

    cudaFuncSetAttribute(attn_h, cudaFuncAttributeMaxDynamicSharedMemorySize, ATTN_SMEM);
    cudaFuncSetAttribute(hgemm_qkv, cudaFuncAttributeMaxDynamicSharedMemorySize, HGEMM_SMEM);
    cudaFuncSetAttribute(hgemm_f, cudaFuncAttributeMaxDynamicSharedMemorySize, HGEMM_SMEM);

    const int M = MTOT;  // 4096

    f2h_kernel<<<(M * DIM / 4 + 255) / 256, 256>>>(x, xh, M * DIM);
    transpose_qkv<<<dim3(96, 64), dim3(32, 8)>>>(Wq, Wk, Wv, wqkvt);
    transpose_h<<<dim3(64, 64), dim3(32, 8)>>>(Wo, wot, DIM, DIM);

    // fused QKV projection (N = 3072)
    hgemm_qkv<<<dim3(24, M / 128), 256, HGEMM_SMEM>>>(xh, wqkvt, qp, kp, vh);

    // rope (q pre-scaled into log2 domain)
    const int qtot4 = MTOT * NH * 8;
    const int ktot4 = MTOT * NKV * 8;
    rope_hh<<<(qtot4 + 255) / 256, 256>>>(qp, qh, NH, qtot4, cs, sn, QSCALE);
    rope_hh<<<(ktot4 + 255) / 256, 256>>>(kp, kh, NKV, ktot4, cs, sn, 1.0f);

    attn_h<<<dim3(SEQ / 128, NH, BATCH), 256, ATTN_SMEM>>>(qh, kh, vh, oh);

    hgemm_f<<<dim3(DIM / 128, M / 128), 256, HGEMM_SMEM>>>(oh, wot, out, DIM, DIM);
}

// round 8
// speedup vs baseline: 7.3622x; 1.0328x over previous
#include <cuda_runtime.h>
#include <cuda_fp16.h>
#include <cstdint>

#define BATCH 2
#define SEQ 2048
#define DIM 2048
#define NH 32
#define NKV 8
#define HD 64
#define MTOT (BATCH * SEQ)
// Q pre-scale: 1/sqrt(64) * log2(e)  (softmax runs in log2 domain)
#define QSCALE 0.18033688011112042f

extern __shared__ char dsmem[];

// Scratch (no cudaMalloc allowed)
__device__ __half g_xh[MTOT * DIM];
__device__ __half g_qp[MTOT * NH * HD];
__device__ __half g_kp[MTOT * NKV * HD];
__device__ __half g_qh[MTOT * NH * HD];
__device__ __half g_kh[MTOT * NKV * HD];
__device__ __half g_vh[MTOT * NKV * HD];
__device__ __half g_oh[MTOT * NH * HD];
__device__ __half g_wqkvt[3072 * DIM];
__device__ __half g_wot[DIM * DIM];

// ---------------------------------------------------------------------------
// helpers
// ---------------------------------------------------------------------------
__device__ __forceinline__ uint32_t smem_u32(const void* p) {
    uint32_t a;
    asm("{ .reg .u64 t; cvta.to.shared.u64 t, %1; cvt.u32.u64 %0, t; }" : "=r"(a) : "l"(p));
    return a;
}

__device__ __forceinline__ void cpa16(uint32_t dst, const void* src) {
    asm volatile("cp.async.cg.shared.global [%0], [%1], 16;" :: "r"(dst), "l"(src) : "memory");
}
#define CP_COMMIT() asm volatile("cp.async.commit_group;" ::: "memory")
#define CP_WAIT1()  asm volatile("cp.async.wait_group 1;" ::: "memory")
#define CP_WAIT2()  asm volatile("cp.async.wait_group 2;" ::: "memory")

__device__ __forceinline__ void ldm_x4(uint32_t r[4], uint32_t addr) {
    asm volatile("ldmatrix.sync.aligned.m8n8.x4.shared.b16 {%0,%1,%2,%3}, [%4];"
                 : "=r"(r[0]), "=r"(r[1]), "=r"(r[2]), "=r"(r[3]) : "r"(addr));
}
__device__ __forceinline__ void ldm_x4t(uint32_t r[4], uint32_t addr) {
    asm volatile("ldmatrix.sync.aligned.m8n8.x4.trans.shared.b16 {%0,%1,%2,%3}, [%4];"
                 : "=r"(r[0]), "=r"(r[1]), "=r"(r[2]), "=r"(r[3]) : "r"(addr));
}

__device__ __forceinline__ void mma_f16(float c[4], const uint32_t a[4],
                                        uint32_t b0, uint32_t b1) {
    asm volatile(
        "mma.sync.aligned.m16n8k16.row.col.f32.f16.f16.f32 "
        "{%0,%1,%2,%3}, {%4,%5,%6,%7}, {%8,%9}, {%0,%1,%2,%3};"
        : "+f"(c[0]), "+f"(c[1]), "+f"(c[2]), "+f"(c[3])
        : "r"(a[0]), "r"(a[1]), "r"(a[2]), "r"(a[3]), "r"(b0), "r"(b1));
}

__device__ __forceinline__ uint32_t ex2h2(float x, float y) {
    __half2 d = __floats2half2_rn(x, y);
    uint32_t e;
    asm("ex2.approx.f16x2 %0, %1;" : "=r"(e) : "r"(*(uint32_t*)&d));
    return e;
}

__device__ __forceinline__ void store2(float* C, size_t off, float x, float y) {
    *(float2*)&C[off] = make_float2(x, y);
}
__device__ __forceinline__ void store2(__half* C, size_t off, float x, float y) {
    *(__half2*)&C[off] = __floats2half2_rn(x, y);
}

// ---------------------------------------------------------------------------
// fp32 -> fp16 elementwise
// ---------------------------------------------------------------------------
__global__ void f2h_kernel(const float* __restrict__ in, __half* __restrict__ out, int n)
{
    int i = (blockIdx.x * blockDim.x + threadIdx.x) * 4;
    if (i < n) {
        float4 v = *(const float4*)&in[i];
        *(__half2*)&out[i]     = __floats2half2_rn(v.x, v.y);
        *(__half2*)&out[i + 2] = __floats2half2_rn(v.z, v.w);
    }
}

// ---------------------------------------------------------------------------
// Combined QKV weight transpose
// ---------------------------------------------------------------------------
__global__ __launch_bounds__(256) void transpose_qkv(
    const float* __restrict__ Wq, const float* __restrict__ Wk,
    const float* __restrict__ Wv, __half* __restrict__ out)
{
    __shared__ float tbuf[32][33];
    const int n0 = blockIdx.x * 32;
    const int k0 = blockIdx.y * 32;
    const float* src; int srcN, nloc;
    if (n0 < 2048)      { src = Wq; srcN = 2048; nloc = n0; }
    else if (n0 < 2560) { src = Wk; srcN = 512;  nloc = n0 - 2048; }
    else                { src = Wv; srcN = 512;  nloc = n0 - 2560; }
    const int tx = threadIdx.x, ty = threadIdx.y;
#pragma unroll
    for (int r = ty; r < 32; r += 8)
        tbuf[r][tx] = src[(size_t)(k0 + r) * srcN + nloc + tx];
    __syncthreads();
#pragma unroll
    for (int r = ty; r < 32; r += 8)
        out[(size_t)(n0 + r) * DIM + k0 + tx] = __float2half(tbuf[tx][r]);
}

__global__ __launch_bounds__(256) void transpose_h(
    const float* __restrict__ in, __half* __restrict__ out, int K, int N)
{
    __shared__ float tbuf[32][33];
    const int k0 = blockIdx.y * 32, n0 = blockIdx.x * 32;
    const int tx = threadIdx.x, ty = threadIdx.y;
#pragma unroll
    for (int r = ty; r < 32; r += 8)
        tbuf[r][tx] = in[(size_t)(k0 + r) * N + n0 + tx];
    __syncthreads();
#pragma unroll
    for (int r = ty; r < 32; r += 8)
        out[(size_t)(n0 + r) * K + k0 + tx] = __float2half(tbuf[tx][r]);
}

// ---------------------------------------------------------------------------
// GEMM core (4-stage cp.async, 128x128 tile, BK=32, 8 warps 2m x 4n)
// ---------------------------------------------------------------------------
#define GPAD 40
#define GBUF (128 * GPAD)
#define STAGES 4
#define HGEMM_SMEM (2 * STAGES * GBUF * 2)   // 81920 B

struct GemmAcc { float a[4][4][4]; };

template <typename EPI>
__device__ __forceinline__ void hgemm_core(
    const __half* Ag0, const __half* Bg0, int K, EPI epi)
{
    __half* Asm = (__half*)dsmem;
    __half* Bsm = Asm + STAGES * GBUF;
    const uint32_t sA = smem_u32(Asm), sB = smem_u32(Bsm);

    const int tid = threadIdx.x, lane = tid & 31, warp = tid >> 5;
    const int wm = warp & 1, wn = warp >> 1;
    const int g = lane >> 2, t = lane & 3;
    const int srow = tid >> 1, sk = (tid & 1) * 16;

    const int ra = (lane & 7) + 8 * ((lane >> 3) & 1);
    const int ca = 8 * (lane >> 4);
    const int rb = (lane & 7) + 8 * (lane >> 4);
    const int cb = 8 * ((lane >> 3) & 1);

    const __half* Ag = Ag0 + (size_t)srow * K + sk;
    const __half* Bg = Bg0 + (size_t)srow * K + sk;
    const uint32_t stOff = (uint32_t)(srow * GPAD + sk) * 2;

    GemmAcc acc;
#pragma unroll
    for (int i = 0; i < 4; i++)
#pragma unroll
        for (int j = 0; j < 4; j++)
#pragma unroll
            for (int c = 0; c < 4; c++) acc.a[i][j][c] = 0.f;

    const int KT = K / 32;
#pragma unroll
    for (int p = 0; p < 3; p++) {
        uint32_t da = sA + p * GBUF * 2 + stOff;
        uint32_t db = sB + p * GBUF * 2 + stOff;
        cpa16(da, Ag + p * 32);  cpa16(da + 16, Ag + p * 32 + 8);
        cpa16(db, Bg + p * 32);  cpa16(db + 16, Bg + p * 32 + 8);
        CP_COMMIT();
    }

    for (int it = 0; it < KT; it++) {
        CP_WAIT2();
        __syncthreads();
        if (it + 3 < KT) {
            const int st = (it + 3) % STAGES;
            uint32_t da = sA + st * GBUF * 2 + stOff;
            uint32_t db = sB + st * GBUF * 2 + stOff;
            cpa16(da, Ag + (it + 3) * 32);  cpa16(da + 16, Ag + (it + 3) * 32 + 8);
            cpa16(db, Bg + (it + 3) * 32);  cpa16(db + 16, Bg + (it + 3) * 32 + 8);
        }
        CP_COMMIT();

        const uint32_t bA = sA + (it % STAGES) * GBUF * 2;
        const uint32_t bB = sB + (it % STAGES) * GBUF * 2;
#pragma unroll
        for (int ks = 0; ks < 2; ks++) {
            const int k0 = ks * 16;
            uint32_t af[4][4];
#pragma unroll
            for (int mt = 0; mt < 4; mt++)
                ldm_x4(af[mt], bA + ((wm * 64 + mt * 16 + ra) * GPAD + k0 + ca) * 2);
#pragma unroll
            for (int bp = 0; bp < 2; bp++) {
                uint32_t b4[4];
                ldm_x4(b4, bB + ((wn * 32 + bp * 16 + rb) * GPAD + k0 + cb) * 2);
#pragma unroll
                for (int mt = 0; mt < 4; mt++) {
                    mma_f16(acc.a[mt][2 * bp],     af[mt], b4[0], b4[1]);
                    mma_f16(acc.a[mt][2 * bp + 1], af[mt], b4[2], b4[3]);
                }
            }
        }
    }
    epi(acc, wm, wn, g, t);
}

// QKV fused projection
__global__ __launch_bounds__(256) void hgemm_qkv(
    const __half* __restrict__ A, const __half* __restrict__ Bt,
    __half* __restrict__ Q, __half* __restrict__ Kc, __half* __restrict__ V)
{
    const int bx = blockIdx.x, by = blockIdx.y;
    __half* Cp; int colbase, stride;
    if (bx < 16)      { Cp = Q;  colbase = bx * 128;        stride = 2048; }
    else if (bx < 20) { Cp = Kc; colbase = (bx - 16) * 128; stride = 512;  }
    else              { Cp = V;  colbase = (bx - 20) * 128; stride = 512;  }
    hgemm_core(A + (size_t)(by * 128) * DIM, Bt + (size_t)(bx * 128) * DIM, DIM,
        [&](const GemmAcc& acc, int wm, int wn, int g, int t) {
#pragma unroll
            for (int mt = 0; mt < 4; mt++) {
                const int row = by * 128 + wm * 64 + mt * 16 + g;
#pragma unroll
                for (int nt = 0; nt < 4; nt++) {
                    const int col = colbase + wn * 32 + nt * 8 + 2 * t;
                    store2(Cp, (size_t)row * stride + col,
                           acc.a[mt][nt][0], acc.a[mt][nt][1]);
                    store2(Cp, (size_t)(row + 8) * stride + col,
                           acc.a[mt][nt][2], acc.a[mt][nt][3]);
                }
            }
        });
}

__global__ __launch_bounds__(256) void hgemm_f(
    const __half* __restrict__ A, const __half* __restrict__ Bt,
    float* __restrict__ C, int N, int K)
{
    const int bx = blockIdx.x, by = blockIdx.y;
    hgemm_core(A + (size_t)(by * 128) * K, Bt + (size_t)(bx * 128) * K, K,
        [&](const GemmAcc& acc, int wm, int wn, int g, int t) {
#pragma unroll
            for (int mt = 0; mt < 4; mt++) {
                const int row = by * 128 + wm * 64 + mt * 16 + g;
#pragma unroll
                for (int nt = 0; nt < 4; nt++) {
                    const int col = bx * 128 + wn * 32 + nt * 8 + 2 * t;
                    store2(C, (size_t)row * N + col, acc.a[mt][nt][0], acc.a[mt][nt][1]);
                    store2(C, (size_t)(row + 8) * N + col, acc.a[mt][nt][2], acc.a[mt][nt][3]);
                }
            }
        });
}

// ---------------------------------------------------------------------------
// RoPE: half in -> half out
// ---------------------------------------------------------------------------
__global__ void rope_hh(const __half* __restrict__ in, __half* __restrict__ out,
                        int nheads, int total4,
                        const float* __restrict__ cs, const float* __restrict__ sn,
                        float scale)
{
    int idx = blockIdx.x * blockDim.x + threadIdx.x;
    if (idx >= total4) return;
    const int d4 = (idx & 7) * 4;
    const int rest = idx >> 3;
    const int s = (rest / nheads) % SEQ;
    const size_t base = (size_t)rest * HD;
    uint2 lo2 = *(const uint2*)&in[base + d4];
    uint2 hi2 = *(const uint2*)&in[base + d4 + 32];
    const __half2* lh = (const __half2*)&lo2;
    const __half2* hh = (const __half2*)&hi2;
    float2 l01 = __half22float2(lh[0]), l23 = __half22float2(lh[1]);
    float2 h01 = __half22float2(hh[0]), h23 = __half22float2(hh[1]);
    float4 c0 = *(const float4*)&cs[s * HD + d4];
    float4 s0 = *(const float4*)&sn[s * HD + d4];
    float4 c1 = *(const float4*)&cs[s * HD + d4 + 32];
    float4 s1 = *(const float4*)&sn[s * HD + d4 + 32];
    *(__half2*)&out[base + d4] = __floats2half2_rn(
        (l01.x * c0.x - h01.x * s0.x) * scale, (l01.y * c0.y - h01.y * s0.y) * scale);
    *(__half2*)&out[base + d4 + 2] = __floats2half2_rn(
        (l23.x * c0.z - h23.x * s0.z) * scale, (l23.y * c0.w - h23.y * s0.w) * scale);
    *(__half2*)&out[base + d4 + 32] = __floats2half2_rn(
        (h01.x * c1.x + l01.x * s1.x) * scale, (h01.y * c1.y + l01.y * s1.y) * scale);
    *(__half2*)&out[base + d4 + 34] = __floats2half2_rn(
        (h23.x * c1.z + l23.x * s1.z) * scale, (h23.y * c1.w + l23.y * s1.w) * scale);
}

// ---------------------------------------------------------------------------
// fp16 flash attention: cp.async KV ring + f16x2 exp + register P
// ---------------------------------------------------------------------------
#define APAD 72
#define KVBUF (64 * APAD)
#define ATTN_SMEM ((128 + 3 * 64 + 3 * 64) * APAD * 2)   // 73728 B

__global__ __launch_bounds__(256) void attn_h(
    const __half* __restrict__ Qg, const __half* __restrict__ Kg,
    const __half* __restrict__ Vg, __half* __restrict__ Og)
{
    __half* Qs = (__half*)dsmem;
    __half* Ks = Qs + 128 * APAD;
    __half* Vs = Ks + 3 * KVBUF;
    const uint32_t sQ = smem_u32(Qs), sK = smem_u32(Ks), sV = smem_u32(Vs);

    const int qb = blockIdx.x, h = blockIdx.y, b = blockIdx.z;
    const int kvh = h >> 2;
    const int tid = threadIdx.x;
    const int warp = tid >> 5, lane = tid & 31;
    const int g = lane >> 2, t = lane & 3;
    const int rowbase = warp * 16;

    const int ra = (lane & 7) + 8 * ((lane >> 3) & 1);
    const int ca = 8 * (lane >> 4);
    const int rb = (lane & 7) + 8 * (lane >> 4);
    const int cb = 8 * ((lane >> 3) & 1);

    const int nchunks = 2 * (qb + 1);
    const int svrow = tid >> 2;
    const int svc   = (tid & 3) * 16;
    const uint32_t kvOff = (uint32_t)(svrow * APAD + svc) * 2;
    const size_t gstride = (size_t)64 * NKV * HD;
    const __half* Kgp = Kg + (((size_t)b * SEQ + svrow) * NKV + kvh) * HD + svc;
    const __half* Vgp = Vg + (((size_t)b * SEQ + svrow) * NKV + kvh) * HD + svc;

#pragma unroll
    for (int p = 0; p < 2; p++) {
        uint32_t dk = sK + p * KVBUF * 2 + kvOff;
        uint32_t dv = sV + p * KVBUF * 2 + kvOff;
        cpa16(dk, Kgp + p * gstride);  cpa16(dk + 16, Kgp + p * gstride + 8);
        cpa16(dv, Vgp + p * gstride);  cpa16(dv + 16, Vgp + p * gstride + 8);
        CP_COMMIT();
    }

    {
        const int row = tid & 127;
        const int c0 = (tid >> 7) * 32;
        const __half* src = &Qg[(((size_t)b * SEQ + qb * 128 + row) * NH + h) * HD + c0];
        uint32_t d = sQ + (row * APAD + c0) * 2;
#pragma unroll
        for (int i = 0; i < 4; i++) {
            uint4 v = *(const uint4*)(src + 8 * i);
            asm volatile("st.shared.v4.b32 [%0], {%1,%2,%3,%4};" :: "r"(d + 16 * i),
                         "r"(v.x), "r"(v.y), "r"(v.z), "r"(v.w) : "memory");
        }
    }
    __syncthreads();

    uint32_t qf[4][4];
#pragma unroll
    for (int kt = 0; kt < 4; kt++)
        ldm_x4(qf[kt], sQ + ((rowbase + ra) * APAD + kt * 16 + ca) * 2);

    float m0r = -1e30f, m1r = -1e30f, l0r = 0.f, l1r = 0.f;
    float of[8][4];
#pragma unroll
    for (int nt = 0; nt < 8; nt++)
#pragma unroll
        for (int c = 0; c < 4; c++) of[nt][c] = 0.f;

    for (int kc = 0; kc < nchunks; kc++) {
        CP_WAIT1();
        __syncthreads();
        if (kc + 2 < nchunks) {
            const int st = (kc + 2) % 3;
            uint32_t dk = sK + st * KVBUF * 2 + kvOff;
            uint32_t dv = sV + st * KVBUF * 2 + kvOff;
            cpa16(dk, Kgp + (size_t)(kc + 2) * gstride);
            cpa16(dk + 16, Kgp + (size_t)(kc + 2) * gstride + 8);
            cpa16(dv, Vgp + (size_t)(kc + 2) * gstride);
            cpa16(dv + 16, Vgp + (size_t)(kc + 2) * gstride + 8);
        }
        CP_COMMIT();

        const uint32_t bK = sK + (kc % 3) * KVBUF * 2;
        const uint32_t bV = sV + (kc % 3) * KVBUF * 2;

        // ---- S = Q K^T (log2-domain scores) ----
        float sf[8][4];
#pragma unroll
        for (int nt = 0; nt < 8; nt++)
#pragma unroll
            for (int c = 0; c < 4; c++) sf[nt][c] = 0.f;

#pragma unroll
        for (int kt = 0; kt < 4; kt++) {
#pragma unroll
            for (int bp = 0; bp < 4; bp++) {
                uint32_t b4[4];
                ldm_x4(b4, bK + ((bp * 16 + rb) * APAD + kt * 16 + cb) * 2);
                mma_f16(sf[2 * bp],     qf[kt], b4[0], b4[1]);
                mma_f16(sf[2 * bp + 1], qf[kt], b4[2], b4[3]);
            }
        }

        // ---- causal mask ----
        const int qr0 = qb * 128 + rowbase + g;
        const int qr1 = qr0 + 8;
        if (kc * 64 + 63 > qr0) {
#pragma unroll
            for (int nt = 0; nt < 8; nt++) {
                const int kv0 = kc * 64 + nt * 8 + 2 * t;
                if (kv0 > qr0)     sf[nt][0] = -1e30f;
                if (kv0 + 1 > qr0) sf[nt][1] = -1e30f;
                if (kv0 > qr1)     sf[nt][2] = -1e30f;
                if (kv0 + 1 > qr1) sf[nt][3] = -1e30f;
            }
        }

        // ---- online softmax: max reduce ----
        float mx0 = -1e30f, mx1 = -1e30f;
#pragma unroll
        for (int nt = 0; nt < 8; nt++) {
            mx0 = fmaxf(mx0, fmaxf(sf[nt][0], sf[nt][1]));
            mx1 = fmaxf(mx1, fmaxf(sf[nt][2], sf[nt][3]));
        }
        mx0 = fmaxf(mx0, __shfl_xor_sync(0xffffffffu, mx0, 1));
        mx0 = fmaxf(mx0, __shfl_xor_sync(0xffffffffu, mx0, 2));
        mx1 = fmaxf(mx1, __shfl_xor_sync(0xffffffffu, mx1, 1));
        mx1 = fmaxf(mx1, __shfl_xor_sync(0xffffffffu, mx1, 2));

        const float mn0 = fmaxf(m0r, mx0);
        const float mn1 = fmaxf(m1r, mx1);
        const float al0 = exp2f(m0r - mn0);
        const float al1 = exp2f(m1r - mn1);
        m0r = mn0; m1r = mn1;

        // ---- exp via f16x2 MUFU; results are the PV A-fragments ----
        uint32_t ph[8][2];
        float ps0 = 0.f, ps1 = 0.f;
#pragma unroll
        for (int nt = 0; nt < 8; nt++) {
            uint32_t e0 = ex2h2(sf[nt][0] - mn0, sf[nt][1] - mn0);
            uint32_t e1 = ex2h2(sf[nt][2] - mn1, sf[nt][3] - mn1);
            ph[nt][0] = e0; ph[nt][1] = e1;
            float2 f0 = __half22float2(*(__half2*)&e0);
            float2 f1 = __half22float2(*(__half2*)&e1);
            ps0 += f0.x + f0.y;
            ps1 += f1.x + f1.y;
        }
        ps0 += __shfl_xor_sync(0xffffffffu, ps0, 1);
        ps0 += __shfl_xor_sync(0xffffffffu, ps0, 2);
        ps1 += __shfl_xor_sync(0xffffffffu, ps1, 1);
        ps1 += __shfl_xor_sync(0xffffffffu, ps1, 2);
        l0r = l0r * al0 + ps0;
        l1r = l1r * al1 + ps1;

#pragma unroll
        for (int nt = 0; nt < 8; nt++) {
            of[nt][0] *= al0; of[nt][1] *= al0;
            of[nt][2] *= al1; of[nt][3] *= al1;
        }

        // ---- O += P @ V ----
#pragma unroll
        for (int j = 0; j < 4; j++) {
            uint32_t pa[4] = { ph[2 * j][0], ph[2 * j][1],
                               ph[2 * j + 1][0], ph[2 * j + 1][1] };
#pragma unroll
            for (int bp = 0; bp < 4; bp++) {
                uint32_t b4[4];
                ldm_x4t(b4, bV + ((j * 16 + ra) * APAD + bp * 16 + ca) * 2);
                mma_f16(of[2 * bp],     pa, b4[0], b4[1]);
                mma_f16(of[2 * bp + 1], pa, b4[2], b4[3]);
            }
        }
    }

    // ---- epilogue ----
    const float inv0 = 1.f / l0r, inv1 = 1.f / l1r;
    const int row0 = qb * 128 + rowbase + g;
#pragma unroll
    for (int nt = 0; nt < 8; nt++) {
        const int col = nt * 8 + 2 * t;
        *(__half2*)&Og[(((size_t)b * SEQ + row0) * NH + h) * HD + col] =
            __floats2half2_rn(of[nt][0] * inv0, of[nt][1] * inv0);
        *(__half2*)&Og[(((size_t)b * SEQ + row0 + 8) * NH + h) * HD + col] =
            __floats2half2_rn(of[nt][2] * inv1, of[nt][3] * inv1);
    }
}

// ---------------------------------------------------------------------------
extern "C" void kernel_launch(void* const* d_in, const int* in_sizes, int n_in,
                              void* d_out, int out_size)
{
    const float* x  = (const float*)d_in[0];
    const float* Wq = (const float*)d_in[1];
    const float* Wk = (const float*)d_in[2];
    const float* Wv = (const float*)d_in[3];
    const float* Wo = (const float*)d_in[4];
    const float* cs = (const float*)d_in[5];
    const float* sn = (const float*)d_in[6];
    float* out = (float*)d_out;

    __half *xh, *qp, *kp, *qh, *kh, *vh, *oh, *wqkvt, *wot;
    cudaGetSymbolAddress((void**)&xh, g_xh);
    cudaGetSymbolAddress((void**)&qp, g_qp);
    cudaGetSymbolAddress((void**)&kp, g_kp);
    cudaGetSymbolAddress((void**)&qh, g_qh);
    cudaGetSymbolAddress((void**)&kh, g_kh);
    cudaGetSymbolAddress((void**)&vh, g_vh);
    cudaGetSymbolAddress((void**)&oh, g_oh);
    cudaGetSymbolAddress((void**)&wqkvt, g_wqkvt);
    cudaGetSymbolAddress((void**)&wot, g_wot);

    cudaFuncSetAttribute(attn_h, cudaFuncAttributeMaxDynamicSharedMemorySize, ATTN_SMEM);
    cudaFuncSetAttribute(hgemm_qkv, cudaFuncAttributeMaxDynamicSharedMemorySize, HGEMM_SMEM);
    cudaFuncSetAttribute(hgemm_f, cudaFuncAttributeMaxDynamicSharedMemorySize, HGEMM_SMEM);

    const int M = MTOT;  // 4096

    f2h_kernel<<<(M * DIM / 4 + 255) / 256, 256>>>(x, xh, M * DIM);
    transpose_qkv<<<dim3(96, 64), dim3(32, 8)>>>(Wq, Wk, Wv, wqkvt);
    transpose_h<<<dim3(64, 64), dim3(32, 8)>>>(Wo, wot, DIM, DIM);

    hgemm_qkv<<<dim3(24, M / 128), 256, HGEMM_SMEM>>>(xh, wqkvt, qp, kp, vh);

    const int qtot4 = MTOT * NH * 8;
    const int ktot4 = MTOT * NKV * 8;
    rope_hh<<<(qtot4 + 255) / 256, 256>>>(qp, qh, NH, qtot4, cs, sn, QSCALE);
    rope_hh<<<(ktot4 + 255) / 256, 256>>>(kp, kh, NKV, ktot4, cs, sn, 1.0f);

    attn_h<<<dim3(SEQ / 128, NH, BATCH), 256, ATTN_SMEM>>>(qh, kh, vh, oh);

    hgemm_f<<<dim3(DIM / 128, M / 128), 256, HGEMM_SMEM>>>(oh, wot, out, DIM, DIM);
}